// round 2
// baseline (speedup 1.0000x reference)
#include <cuda_runtime.h>
#include <math.h>

#define Bn 4
#define Sn 2048
#define Dn 1024
#define Hn 16
#define HDn 64
#define Mn 8192          // B*S

// ---- scratch (allocation-free rule: __device__ globals) ----
__device__ float g_ln1[(size_t)Mn * Dn];        // 32 MB
__device__ float g_qkv[(size_t)Mn * 3 * Dn];    // 96 MB
__device__ float g_att[(size_t)Mn * Dn];        // 32 MB
__device__ float g_x1 [(size_t)Mn * Dn];        // 32 MB
__device__ float g_ln2[(size_t)Mn * Dn];        // 32 MB
__device__ float g_fc [(size_t)Mn * 4 * Dn];    // 128 MB

// ---------------- LayerNorm: one block per row ----------------
__global__ void __launch_bounds__(256) ln_kernel(const float* __restrict__ x,
                                                 const float* __restrict__ g,
                                                 const float* __restrict__ bta,
                                                 float* __restrict__ out)
{
    int row = blockIdx.x;
    const float* xr = x + (size_t)row * Dn;
    float* orow = out + (size_t)row * Dn;
    float s = 0.f, s2 = 0.f;
    for (int i = threadIdx.x; i < Dn; i += 256) {
        float v = xr[i];
        s += v;
        s2 = fmaf(v, v, s2);
    }
    #pragma unroll
    for (int off = 16; off; off >>= 1) {
        s  += __shfl_xor_sync(0xffffffffu, s,  off);
        s2 += __shfl_xor_sync(0xffffffffu, s2, off);
    }
    __shared__ float rs[8], rs2[8];
    int w = threadIdx.x >> 5, lane = threadIdx.x & 31;
    if (lane == 0) { rs[w] = s; rs2[w] = s2; }
    __syncthreads();
    if (threadIdx.x < 32) {
        s  = (lane < 8) ? rs[lane]  : 0.f;
        s2 = (lane < 8) ? rs2[lane] : 0.f;
        #pragma unroll
        for (int off = 4; off; off >>= 1) {
            s  += __shfl_xor_sync(0xffffffffu, s,  off);
            s2 += __shfl_xor_sync(0xffffffffu, s2, off);
        }
        if (lane == 0) { rs[0] = s; rs2[0] = s2; }
    }
    __syncthreads();
    float mu  = rs[0] * (1.f / Dn);
    float var = rs2[0] * (1.f / Dn) - mu * mu;
    float inv = rsqrtf(var + 1e-5f);
    for (int i = threadIdx.x; i < Dn; i += 256) {
        orow[i] = (xr[i] - mu) * inv * g[i] + bta[i];
    }
}

// ---------------- GEMM: 128x128 tile, BK=8, 8x8 per thread ----------------
// EPI: 0 = +bias, 1 = +bias +residual, 2 = +bias then exact GELU
__device__ __forceinline__ float gelu_exact(float v) {
    return 0.5f * v * (1.0f + erff(v * 0.7071067811865476f));
}

template<int EPI>
__global__ void __launch_bounds__(256) gemm_kernel(
    const float* __restrict__ A, const float* __restrict__ W,
    const float* __restrict__ bias, const float* __restrict__ res,
    float* __restrict__ C, int M, int N, int K)
{
    __shared__ float As[8][128];
    __shared__ float Bs[8][128];
    int tid = threadIdx.x;
    int rowBase = blockIdx.y * 128;
    int colBase = blockIdx.x * 128;
    int tr = tid >> 4, tc = tid & 15;

    int arow = tid >> 1;
    int acol = (tid & 1) << 2;
    int bkrow = tid >> 5;
    int bcol  = (tid & 31) << 2;

    const float* Ap = A + (size_t)(rowBase + arow) * K + acol;
    const float* Bp = W + (size_t)bkrow * N + colBase + bcol;

    float acc[8][8];
    #pragma unroll
    for (int i = 0; i < 8; i++)
        #pragma unroll
        for (int j = 0; j < 8; j++) acc[i][j] = 0.f;

    int nk = K >> 3;
    for (int kb = 0; kb < nk; kb++) {
        float4 a4 = *(const float4*)Ap;
        float4 b4 = *(const float4*)Bp;
        __syncthreads();
        As[acol + 0][arow] = a4.x;
        As[acol + 1][arow] = a4.y;
        As[acol + 2][arow] = a4.z;
        As[acol + 3][arow] = a4.w;
        *(float4*)&Bs[bkrow][bcol] = b4;
        __syncthreads();
        Ap += 8;
        Bp += (size_t)8 * N;
        #pragma unroll
        for (int k = 0; k < 8; k++) {
            float ra[8], rb[8];
            *(float4*)&ra[0] = *(const float4*)&As[k][tr * 8];
            *(float4*)&ra[4] = *(const float4*)&As[k][tr * 8 + 4];
            *(float4*)&rb[0] = *(const float4*)&Bs[k][tc * 8];
            *(float4*)&rb[4] = *(const float4*)&Bs[k][tc * 8 + 4];
            #pragma unroll
            for (int i = 0; i < 8; i++)
                #pragma unroll
                for (int j = 0; j < 8; j++)
                    acc[i][j] = fmaf(ra[i], rb[j], acc[i][j]);
        }
    }

    #pragma unroll
    for (int i = 0; i < 8; i++) {
        int row = rowBase + tr * 8 + i;
        #pragma unroll
        for (int j = 0; j < 8; j++) {
            int col = colBase + tc * 8 + j;
            float v = acc[i][j] + bias[col];
            if (EPI == 1) v += res[(size_t)row * N + col];
            if (EPI == 2) v = gelu_exact(v);
            C[(size_t)row * N + col] = v;
        }
    }
}

// ---------------- Flash attention (causal), fp32 ----------------
// grid: (S/64, B*H); block 256 threads as 16x16; smem 4 tiles of 64x65 f32
#define ATTN_SMEM (4 * 64 * 65 * 4)

__global__ void __launch_bounds__(256) attn_kernel(const float* __restrict__ qkv,
                                                   float* __restrict__ out)
{
    extern __shared__ float sm[];
    float* Qs = sm;
    float* Ks = sm + 64 * 65;
    float* Vs = sm + 2 * 64 * 65;
    float* Ps = sm + 3 * 64 * 65;

    int bh = blockIdx.y;
    int b = bh >> 4;       // H = 16
    int h = bh & 15;
    int q0 = blockIdx.x * 64;
    int tid = threadIdx.x;
    int ty = tid >> 4, tx = tid & 15;

    const size_t rowstride = 3 * Dn;
    const float* base = qkv + (size_t)b * Sn * rowstride + (size_t)h * HDn;

    // load Q tile (64 x 64)
    {
        int r = tid >> 4;
        int c = (tid & 15) * 4;
        #pragma unroll
        for (int it = 0; it < 4; it++) {
            int rr = r + it * 16;
            const float* p = base + (size_t)(q0 + rr) * rowstride + c;
            float4 v = *(const float4*)p;
            float* q = &Qs[rr * 65 + c];
            q[0] = v.x; q[1] = v.y; q[2] = v.z; q[3] = v.w;
        }
    }

    float m[4], l[4], o[4][4];
    #pragma unroll
    for (int i = 0; i < 4; i++) {
        m[i] = -1e30f; l[i] = 0.f;
        #pragma unroll
        for (int j = 0; j < 4; j++) o[i][j] = 0.f;
    }

    int ntiles = blockIdx.x + 1;  // causal: kv tiles with j0 <= q0
    for (int jt = 0; jt < ntiles; jt++) {
        int j0 = jt * 64;
        __syncthreads();  // prior iteration done with Ks/Vs/Ps
        // load K,V tiles
        {
            int r = tid >> 4;
            int c = (tid & 15) * 4;
            #pragma unroll
            for (int it = 0; it < 4; it++) {
                int rr = r + it * 16;
                const float* pk = base + Dn     + (size_t)(j0 + rr) * rowstride + c;
                const float* pv = base + 2 * Dn + (size_t)(j0 + rr) * rowstride + c;
                float4 kv = *(const float4*)pk;
                float4 vv = *(const float4*)pv;
                float* kd = &Ks[rr * 65 + c];
                kd[0] = kv.x; kd[1] = kv.y; kd[2] = kv.z; kd[3] = kv.w;
                float* vd = &Vs[rr * 65 + c];
                vd[0] = vv.x; vd[1] = vv.y; vd[2] = vv.z; vd[3] = vv.w;
            }
        }
        __syncthreads();

        // S = Q K^T (64x64), each thread 4x4
        float s[4][4];
        #pragma unroll
        for (int i = 0; i < 4; i++)
            #pragma unroll
            for (int j = 0; j < 4; j++) s[i][j] = 0.f;
        for (int d = 0; d < 64; d++) {
            float qv[4], kv[4];
            #pragma unroll
            for (int i = 0; i < 4; i++) qv[i] = Qs[(ty * 4 + i) * 65 + d];
            #pragma unroll
            for (int j = 0; j < 4; j++) kv[j] = Ks[(tx * 4 + j) * 65 + d];
            #pragma unroll
            for (int i = 0; i < 4; i++)
                #pragma unroll
                for (int j = 0; j < 4; j++)
                    s[i][j] = fmaf(qv[i], kv[j], s[i][j]);
        }

        bool diag = (jt == blockIdx.x);
        #pragma unroll
        for (int i = 0; i < 4; i++) {
            int qi = ty * 4 + i;
            #pragma unroll
            for (int j = 0; j < 4; j++) {
                int kj = tx * 4 + j;
                float v = s[i][j] * 0.125f;   // 1/sqrt(64)
                if (diag && kj > qi) v = -1e30f;
                s[i][j] = v;
            }
        }

        // online softmax (row groups = 16 lanes sharing ty)
        #pragma unroll
        for (int i = 0; i < 4; i++) {
            float mx = fmaxf(fmaxf(s[i][0], s[i][1]), fmaxf(s[i][2], s[i][3]));
            #pragma unroll
            for (int off = 8; off; off >>= 1)
                mx = fmaxf(mx, __shfl_xor_sync(0xffffffffu, mx, off, 16));
            float mnew = fmaxf(m[i], mx);
            float alpha = __expf(m[i] - mnew);
            m[i] = mnew;
            float rsum = 0.f;
            #pragma unroll
            for (int j = 0; j < 4; j++) {
                float p = __expf(s[i][j] - mnew);
                s[i][j] = p;
                rsum += p;
            }
            #pragma unroll
            for (int off = 8; off; off >>= 1)
                rsum += __shfl_xor_sync(0xffffffffu, rsum, off, 16);
            l[i] = l[i] * alpha + rsum;
            #pragma unroll
            for (int j = 0; j < 4; j++) o[i][j] *= alpha;
        }

        // stage P to smem for the PV product
        #pragma unroll
        for (int i = 0; i < 4; i++)
            #pragma unroll
            for (int j = 0; j < 4; j++)
                Ps[(ty * 4 + i) * 65 + tx * 4 + j] = s[i][j];
        __syncthreads();

        // O += P @ V
        for (int c = 0; c < 64; c++) {
            float pv[4], vv[4];
            #pragma unroll
            for (int i = 0; i < 4; i++) pv[i] = Ps[(ty * 4 + i) * 65 + c];
            #pragma unroll
            for (int j = 0; j < 4; j++) vv[j] = Vs[c * 65 + tx * 4 + j];
            #pragma unroll
            for (int i = 0; i < 4; i++)
                #pragma unroll
                for (int j = 0; j < 4; j++)
                    o[i][j] = fmaf(pv[i], vv[j], o[i][j]);
        }
    }

    // normalize + write [B,S,D] with head offset
    #pragma unroll
    for (int i = 0; i < 4; i++) {
        int qi = q0 + ty * 4 + i;
        float invl = 1.f / l[i];
        #pragma unroll
        for (int j = 0; j < 4; j++) {
            out[((size_t)b * Sn + qi) * Dn + h * HDn + tx * 4 + j] = o[i][j] * invl;
        }
    }
}

// ---------------- launch ----------------
extern "C" void kernel_launch(void* const* d_in, const int* in_sizes, int n_in,
                              void* d_out, int out_size)
{
    const float* x     = (const float*)d_in[0];
    // d_in[1] attention_mask: pure causal, handled analytically
    const float* ln1_g = (const float*)d_in[2];
    const float* ln1_b = (const float*)d_in[3];
    const float* w_qkv = (const float*)d_in[4];
    const float* b_qkv = (const float*)d_in[5];
    const float* w_ao  = (const float*)d_in[6];
    const float* b_ao  = (const float*)d_in[7];
    const float* ln2_g = (const float*)d_in[8];
    const float* ln2_b = (const float*)d_in[9];
    const float* w_fc  = (const float*)d_in[10];
    const float* b_fc  = (const float*)d_in[11];
    const float* w_out = (const float*)d_in[12];
    const float* b_out = (const float*)d_in[13];
    float* out = (float*)d_out;

    float *p_ln1, *p_qkv, *p_att, *p_x1, *p_ln2, *p_fc;
    cudaGetSymbolAddress((void**)&p_ln1, g_ln1);
    cudaGetSymbolAddress((void**)&p_qkv, g_qkv);
    cudaGetSymbolAddress((void**)&p_att, g_att);
    cudaGetSymbolAddress((void**)&p_x1,  g_x1);
    cudaGetSymbolAddress((void**)&p_ln2, g_ln2);
    cudaGetSymbolAddress((void**)&p_fc,  g_fc);

    cudaFuncSetAttribute(attn_kernel, cudaFuncAttributeMaxDynamicSharedMemorySize, ATTN_SMEM);

    // 1) LN1
    ln_kernel<<<Mn, 256>>>(x, ln1_g, ln1_b, p_ln1);
    // 2) QKV = LN1 @ w_qkv + b_qkv   [8192 x 3072]
    gemm_kernel<0><<<dim3(3 * Dn / 128, Mn / 128), 256>>>(p_ln1, w_qkv, b_qkv, nullptr, p_qkv, Mn, 3 * Dn, Dn);
    // 3) causal flash attention
    attn_kernel<<<dim3(Sn / 64, Bn * Hn), 256, ATTN_SMEM>>>(p_qkv, p_att);
    // 4) x1 = x + att @ w_ao + b_ao
    gemm_kernel<1><<<dim3(Dn / 128, Mn / 128), 256>>>(p_att, w_ao, b_ao, x, p_x1, Mn, Dn, Dn);
    // 5) LN2
    ln_kernel<<<Mn, 256>>>(p_x1, ln2_g, ln2_b, p_ln2);
    // 6) fc = gelu(LN2 @ w_fc + b_fc)  [8192 x 4096]
    gemm_kernel<2><<<dim3(4 * Dn / 128, Mn / 128), 256>>>(p_ln2, w_fc, b_fc, nullptr, p_fc, Mn, 4 * Dn, Dn);
    // 7) out = x1 + fc @ w_out + b_out
    gemm_kernel<1><<<dim3(Dn / 128, Mn / 128), 256>>>(p_fc, w_out, b_out, p_x1, out, Mn, Dn, 4 * Dn);
}

// round 4
// speedup vs baseline: 1.7810x; 1.7810x over previous
#include <cuda_runtime.h>
#include <stdint.h>
#include <math.h>

#define Bn 4
#define Sn 2048
#define Dn 1024
#define Hn 16
#define HDn 64
#define Mn 8192          // B*S

// ---- scratch (allocation-free rule: __device__ globals) ----
__device__ float g_ln1[(size_t)Mn * Dn];        // 32 MB
__device__ float g_qkv[(size_t)Mn * 3 * Dn];    // 96 MB
__device__ float g_att[(size_t)Mn * Dn];        // 32 MB
__device__ float g_x1 [(size_t)Mn * Dn];        // 32 MB
__device__ float g_ln2[(size_t)Mn * Dn];        // 32 MB
__device__ float g_fc [(size_t)Mn * 4 * Dn];    // 128 MB

// ---------------- LayerNorm: one block per row ----------------
__global__ void __launch_bounds__(256) ln_kernel(const float* __restrict__ x,
                                                 const float* __restrict__ g,
                                                 const float* __restrict__ bta,
                                                 float* __restrict__ out)
{
    int row = blockIdx.x;
    const float* xr = x + (size_t)row * Dn;
    float* orow = out + (size_t)row * Dn;
    float s = 0.f, s2 = 0.f;
    for (int i = threadIdx.x; i < Dn; i += 256) {
        float v = xr[i];
        s += v;
        s2 = fmaf(v, v, s2);
    }
    #pragma unroll
    for (int off = 16; off; off >>= 1) {
        s  += __shfl_xor_sync(0xffffffffu, s,  off);
        s2 += __shfl_xor_sync(0xffffffffu, s2, off);
    }
    __shared__ float rs[8], rs2[8];
    int w = threadIdx.x >> 5, lane = threadIdx.x & 31;
    if (lane == 0) { rs[w] = s; rs2[w] = s2; }
    __syncthreads();
    if (threadIdx.x < 32) {
        s  = (lane < 8) ? rs[lane]  : 0.f;
        s2 = (lane < 8) ? rs2[lane] : 0.f;
        #pragma unroll
        for (int off = 4; off; off >>= 1) {
            s  += __shfl_xor_sync(0xffffffffu, s,  off);
            s2 += __shfl_xor_sync(0xffffffffu, s2, off);
        }
        if (lane == 0) { rs[0] = s; rs2[0] = s2; }
    }
    __syncthreads();
    float mu  = rs[0] * (1.f / Dn);
    float var = rs2[0] * (1.f / Dn) - mu * mu;
    float inv = rsqrtf(var + 1e-5f);
    for (int i = threadIdx.x; i < Dn; i += 256) {
        orow[i] = (xr[i] - mu) * inv * g[i] + bta[i];
    }
}

// =====================================================================
// TF32 tensor-core GEMM: 128x128 CTA tile, BK=16, 128 threads (4 warps),
// each warp computes a 64x64 tile via mma.sync.m16n8k8 (tf32).
// EPI: 0 = +bias, 1 = +bias +residual, 2 = +bias then exact GELU
// =====================================================================
__device__ __forceinline__ float gelu_exact(float v) {
    return 0.5f * v * (1.0f + erff(v * 0.7071067811865476f));
}
__device__ __forceinline__ uint32_t f2tf(float f) {
    uint32_t u;
    asm("cvt.rna.tf32.f32 %0, %1;" : "=r"(u) : "f"(f));
    return u;
}

#define SPAD 136   // 128 + 8 pad: fragment loads hit banks (8c + r) -> conflict-free

template<int EPI>
__global__ void __launch_bounds__(128) gemm_tf32(
    const float* __restrict__ A, const float* __restrict__ W,
    const float* __restrict__ bias, const float* __restrict__ res,
    float* __restrict__ C, int M, int N, int K)
{
    __shared__ uint32_t As[16 * SPAD];   // [k][m], tf32 bits
    __shared__ uint32_t Bs[16 * SPAD];   // [k][n], tf32 bits

    int tid = threadIdx.x;
    int lane = tid & 31, wid = tid >> 5;
    int warp_m = wid >> 1, warp_n = wid & 1;
    int r = lane >> 2, c = lane & 3;

    int rowBase = blockIdx.y * 128;
    int colBase = blockIdx.x * 128;

    // A: thread `tid` owns row `tid`, loads the 16-wide k-slice as 4 float4
    const float* Ap = A + (size_t)(rowBase + tid) * K;
    // B: thread handles (k = tid>>5 + 4j, n4 = tid&31), j = 0..3
    int bk0 = tid >> 5;
    int bn4 = tid & 31;
    const float* Bp = W + (size_t)bk0 * N + colBase + bn4 * 4;

    float acc[4][8][4];
    #pragma unroll
    for (int mi = 0; mi < 4; mi++)
        #pragma unroll
        for (int ni = 0; ni < 8; ni++)
            #pragma unroll
            for (int e = 0; e < 4; e++) acc[mi][ni][e] = 0.f;

    int nk = K >> 4;
    for (int kb = 0; kb < nk; kb++) {
        // prefetch gmem into registers
        float4 apf[4];
        #pragma unroll
        for (int j = 0; j < 4; j++)
            apf[j] = *(const float4*)(Ap + kb * 16 + j * 4);
        float4 bpf[4];
        #pragma unroll
        for (int j = 0; j < 4; j++)
            bpf[j] = *(const float4*)(Bp + (size_t)(kb * 16 + j * 4) * N);

        __syncthreads();   // previous compute done reading smem

        // A: transpose-store, conflict-free (bank = tid mod 32 per STS)
        #pragma unroll
        for (int j = 0; j < 4; j++) {
            As[(j * 4 + 0) * SPAD + tid] = f2tf(apf[j].x);
            As[(j * 4 + 1) * SPAD + tid] = f2tf(apf[j].y);
            As[(j * 4 + 2) * SPAD + tid] = f2tf(apf[j].z);
            As[(j * 4 + 3) * SPAD + tid] = f2tf(apf[j].w);
        }
        // B: natural layout, STS.128 conflict-free
        #pragma unroll
        for (int j = 0; j < 4; j++) {
            uint4 bb;
            bb.x = f2tf(bpf[j].x); bb.y = f2tf(bpf[j].y);
            bb.z = f2tf(bpf[j].z); bb.w = f2tf(bpf[j].w);
            *(uint4*)&Bs[(bk0 + j * 4) * SPAD + bn4 * 4] = bb;
        }
        __syncthreads();

        // compute: 2 k-steps of 8
        #pragma unroll
        for (int ks = 0; ks < 2; ks++) {
            int kk = ks * 8;
            uint32_t af[4][4], bf[8][2];
            #pragma unroll
            for (int mi = 0; mi < 4; mi++) {
                int m0 = warp_m * 64 + mi * 16 + r;
                af[mi][0] = As[(kk + c) * SPAD + m0];
                af[mi][1] = As[(kk + c) * SPAD + m0 + 8];
                af[mi][2] = As[(kk + c + 4) * SPAD + m0];
                af[mi][3] = As[(kk + c + 4) * SPAD + m0 + 8];
            }
            #pragma unroll
            for (int ni = 0; ni < 8; ni++) {
                int n0 = warp_n * 64 + ni * 8 + r;
                bf[ni][0] = Bs[(kk + c) * SPAD + n0];
                bf[ni][1] = Bs[(kk + c + 4) * SPAD + n0];
            }
            #pragma unroll
            for (int mi = 0; mi < 4; mi++)
                #pragma unroll
                for (int ni = 0; ni < 8; ni++) {
                    asm volatile(
                        "mma.sync.aligned.m16n8k8.row.col.f32.tf32.tf32.f32 "
                        "{%0,%1,%2,%3}, {%4,%5,%6,%7}, {%8,%9}, {%0,%1,%2,%3};\n"
                        : "+f"(acc[mi][ni][0]), "+f"(acc[mi][ni][1]),
                          "+f"(acc[mi][ni][2]), "+f"(acc[mi][ni][3])
                        : "r"(af[mi][0]), "r"(af[mi][1]), "r"(af[mi][2]), "r"(af[mi][3]),
                          "r"(bf[ni][0]), "r"(bf[ni][1]));
                }
        }
    }

    // epilogue: c0,c1 at (r, 2c..2c+1); c2,c3 at (r+8, 2c..2c+1)
    #pragma unroll
    for (int mi = 0; mi < 4; mi++) {
        int row0 = rowBase + warp_m * 64 + mi * 16 + r;
        #pragma unroll
        for (int ni = 0; ni < 8; ni++) {
            int col = colBase + warp_n * 64 + ni * 8 + 2 * c;
            float b0 = bias[col], b1 = bias[col + 1];
            float v0 = acc[mi][ni][0] + b0;
            float v1 = acc[mi][ni][1] + b1;
            float v2 = acc[mi][ni][2] + b0;
            float v3 = acc[mi][ni][3] + b1;
            if (EPI == 1) {
                const float2 r0 = *(const float2*)&res[(size_t)row0 * N + col];
                const float2 r1 = *(const float2*)&res[(size_t)(row0 + 8) * N + col];
                v0 += r0.x; v1 += r0.y; v2 += r1.x; v3 += r1.y;
            }
            if (EPI == 2) {
                v0 = gelu_exact(v0); v1 = gelu_exact(v1);
                v2 = gelu_exact(v2); v3 = gelu_exact(v3);
            }
            *(float2*)&C[(size_t)row0 * N + col]       = make_float2(v0, v1);
            *(float2*)&C[(size_t)(row0 + 8) * N + col] = make_float2(v2, v3);
        }
    }
}

// ---------------- Flash attention (causal), fp32 ----------------
// grid: (S/64, B*H); block 256 threads as 16x16; smem 4 tiles of 64x65 f32
#define ATTN_SMEM (4 * 64 * 65 * 4)

__global__ void __launch_bounds__(256) attn_kernel(const float* __restrict__ qkv,
                                                   float* __restrict__ out)
{
    extern __shared__ float sm[];
    float* Qs = sm;
    float* Ks = sm + 64 * 65;
    float* Vs = sm + 2 * 64 * 65;
    float* Ps = sm + 3 * 64 * 65;

    int bh = blockIdx.y;
    int b = bh >> 4;       // H = 16
    int h = bh & 15;
    int q0 = blockIdx.x * 64;
    int tid = threadIdx.x;
    int ty = tid >> 4, tx = tid & 15;

    const size_t rowstride = 3 * Dn;
    const float* base = qkv + (size_t)b * Sn * rowstride + (size_t)h * HDn;

    // load Q tile (64 x 64)
    {
        int r = tid >> 4;
        int c = (tid & 15) * 4;
        #pragma unroll
        for (int it = 0; it < 4; it++) {
            int rr = r + it * 16;
            const float* p = base + (size_t)(q0 + rr) * rowstride + c;
            float4 v = *(const float4*)p;
            float* q = &Qs[rr * 65 + c];
            q[0] = v.x; q[1] = v.y; q[2] = v.z; q[3] = v.w;
        }
    }

    float m[4], l[4], o[4][4];
    #pragma unroll
    for (int i = 0; i < 4; i++) {
        m[i] = -1e30f; l[i] = 0.f;
        #pragma unroll
        for (int j = 0; j < 4; j++) o[i][j] = 0.f;
    }

    int ntiles = blockIdx.x + 1;  // causal: kv tiles with j0 <= q0
    for (int jt = 0; jt < ntiles; jt++) {
        int j0 = jt * 64;
        __syncthreads();  // prior iteration done with Ks/Vs/Ps
        // load K,V tiles
        {
            int r = tid >> 4;
            int c = (tid & 15) * 4;
            #pragma unroll
            for (int it = 0; it < 4; it++) {
                int rr = r + it * 16;
                const float* pk = base + Dn     + (size_t)(j0 + rr) * rowstride + c;
                const float* pv = base + 2 * Dn + (size_t)(j0 + rr) * rowstride + c;
                float4 kv = *(const float4*)pk;
                float4 vv = *(const float4*)pv;
                float* kd = &Ks[rr * 65 + c];
                kd[0] = kv.x; kd[1] = kv.y; kd[2] = kv.z; kd[3] = kv.w;
                float* vd = &Vs[rr * 65 + c];
                vd[0] = vv.x; vd[1] = vv.y; vd[2] = vv.z; vd[3] = vv.w;
            }
        }
        __syncthreads();

        // S = Q K^T (64x64), each thread 4x4
        float s[4][4];
        #pragma unroll
        for (int i = 0; i < 4; i++)
            #pragma unroll
            for (int j = 0; j < 4; j++) s[i][j] = 0.f;
        for (int d = 0; d < 64; d++) {
            float qv[4], kv[4];
            #pragma unroll
            for (int i = 0; i < 4; i++) qv[i] = Qs[(ty * 4 + i) * 65 + d];
            #pragma unroll
            for (int j = 0; j < 4; j++) kv[j] = Ks[(tx * 4 + j) * 65 + d];
            #pragma unroll
            for (int i = 0; i < 4; i++)
                #pragma unroll
                for (int j = 0; j < 4; j++)
                    s[i][j] = fmaf(qv[i], kv[j], s[i][j]);
        }

        bool diag = (jt == blockIdx.x);
        #pragma unroll
        for (int i = 0; i < 4; i++) {
            int qi = ty * 4 + i;
            #pragma unroll
            for (int j = 0; j < 4; j++) {
                int kj = tx * 4 + j;
                float v = s[i][j] * 0.125f;   // 1/sqrt(64)
                if (diag && kj > qi) v = -1e30f;
                s[i][j] = v;
            }
        }

        // online softmax (row groups = 16 lanes sharing ty)
        #pragma unroll
        for (int i = 0; i < 4; i++) {
            float mx = fmaxf(fmaxf(s[i][0], s[i][1]), fmaxf(s[i][2], s[i][3]));
            #pragma unroll
            for (int off = 8; off; off >>= 1)
                mx = fmaxf(mx, __shfl_xor_sync(0xffffffffu, mx, off, 16));
            float mnew = fmaxf(m[i], mx);
            float alpha = __expf(m[i] - mnew);
            m[i] = mnew;
            float rsum = 0.f;
            #pragma unroll
            for (int j = 0; j < 4; j++) {
                float p = __expf(s[i][j] - mnew);
                s[i][j] = p;
                rsum += p;
            }
            #pragma unroll
            for (int off = 8; off; off >>= 1)
                rsum += __shfl_xor_sync(0xffffffffu, rsum, off, 16);
            l[i] = l[i] * alpha + rsum;
            #pragma unroll
            for (int j = 0; j < 4; j++) o[i][j] *= alpha;
        }

        // stage P to smem for the PV product
        #pragma unroll
        for (int i = 0; i < 4; i++)
            #pragma unroll
            for (int j = 0; j < 4; j++)
                Ps[(ty * 4 + i) * 65 + tx * 4 + j] = s[i][j];
        __syncthreads();

        // O += P @ V
        for (int c = 0; c < 64; c++) {
            float pv[4], vv[4];
            #pragma unroll
            for (int i = 0; i < 4; i++) pv[i] = Ps[(ty * 4 + i) * 65 + c];
            #pragma unroll
            for (int j = 0; j < 4; j++) vv[j] = Vs[c * 65 + tx * 4 + j];
            #pragma unroll
            for (int i = 0; i < 4; i++)
                #pragma unroll
                for (int j = 0; j < 4; j++)
                    o[i][j] = fmaf(pv[i], vv[j], o[i][j]);
        }
    }

    // normalize + write [B,S,D] with head offset
    #pragma unroll
    for (int i = 0; i < 4; i++) {
        int qi = q0 + ty * 4 + i;
        float invl = 1.f / l[i];
        #pragma unroll
        for (int j = 0; j < 4; j++) {
            out[((size_t)b * Sn + qi) * Dn + h * HDn + tx * 4 + j] = o[i][j] * invl;
        }
    }
}

// ---------------- launch ----------------
extern "C" void kernel_launch(void* const* d_in, const int* in_sizes, int n_in,
                              void* d_out, int out_size)
{
    const float* x     = (const float*)d_in[0];
    // d_in[1] attention_mask: pure causal, handled analytically
    const float* ln1_g = (const float*)d_in[2];
    const float* ln1_b = (const float*)d_in[3];
    const float* w_qkv = (const float*)d_in[4];
    const float* b_qkv = (const float*)d_in[5];
    const float* w_ao  = (const float*)d_in[6];
    const float* b_ao  = (const float*)d_in[7];
    const float* ln2_g = (const float*)d_in[8];
    const float* ln2_b = (const float*)d_in[9];
    const float* w_fc  = (const float*)d_in[10];
    const float* b_fc  = (const float*)d_in[11];
    const float* w_out = (const float*)d_in[12];
    const float* b_out = (const float*)d_in[13];
    float* out = (float*)d_out;

    float *p_ln1, *p_qkv, *p_att, *p_x1, *p_ln2, *p_fc;
    cudaGetSymbolAddress((void**)&p_ln1, g_ln1);
    cudaGetSymbolAddress((void**)&p_qkv, g_qkv);
    cudaGetSymbolAddress((void**)&p_att, g_att);
    cudaGetSymbolAddress((void**)&p_x1,  g_x1);
    cudaGetSymbolAddress((void**)&p_ln2, g_ln2);
    cudaGetSymbolAddress((void**)&p_fc,  g_fc);

    cudaFuncSetAttribute(attn_kernel, cudaFuncAttributeMaxDynamicSharedMemorySize, ATTN_SMEM);

    // 1) LN1
    ln_kernel<<<Mn, 256>>>(x, ln1_g, ln1_b, p_ln1);
    // 2) QKV = LN1 @ w_qkv + b_qkv   [8192 x 3072]
    gemm_tf32<0><<<dim3(3 * Dn / 128, Mn / 128), 128>>>(p_ln1, w_qkv, b_qkv, nullptr, p_qkv, Mn, 3 * Dn, Dn);
    // 3) causal flash attention
    attn_kernel<<<dim3(Sn / 64, Bn * Hn), 256, ATTN_SMEM>>>(p_qkv, p_att);
    // 4) x1 = x + att @ w_ao + b_ao
    gemm_tf32<1><<<dim3(Dn / 128, Mn / 128), 128>>>(p_att, w_ao, b_ao, x, p_x1, Mn, Dn, Dn);
    // 5) LN2
    ln_kernel<<<Mn, 256>>>(p_x1, ln2_g, ln2_b, p_ln2);
    // 6) fc = gelu(LN2 @ w_fc + b_fc)  [8192 x 4096]
    gemm_tf32<2><<<dim3(4 * Dn / 128, Mn / 128), 128>>>(p_ln2, w_fc, b_fc, nullptr, p_fc, Mn, 4 * Dn, Dn);
    // 7) out = x1 + fc @ w_out + b_out
    gemm_tf32<1><<<dim3(Dn / 128, Mn / 128), 128>>>(p_fc, w_out, b_out, p_x1, out, Mn, Dn, 4 * Dn);
}

// round 8
// speedup vs baseline: 2.0489x; 1.1504x over previous
#include <cuda_runtime.h>
#include <stdint.h>
#include <math.h>

#define Bn 4
#define Sn 2048
#define Dn 1024
#define Hn 16
#define HDn 64
#define Mn 8192          // B*S

// ---- scratch (allocation-free rule: __device__ globals) ----
__device__ float g_ln1[(size_t)Mn * Dn];        // 32 MB
__device__ float g_qkv[(size_t)Mn * 3 * Dn];    // 96 MB
__device__ float g_att[(size_t)Mn * Dn];        // 32 MB
__device__ float g_x1 [(size_t)Mn * Dn];        // 32 MB
__device__ float g_ln2[(size_t)Mn * Dn];        // 32 MB
__device__ float g_fc [(size_t)Mn * 4 * Dn];    // 128 MB

// ---------------- LayerNorm: one block per row ----------------
__global__ void __launch_bounds__(256) ln_kernel(const float* __restrict__ x,
                                                 const float* __restrict__ g,
                                                 const float* __restrict__ bta,
                                                 float* __restrict__ out)
{
    int row = blockIdx.x;
    const float* xr = x + (size_t)row * Dn;
    float* orow = out + (size_t)row * Dn;
    float s = 0.f, s2 = 0.f;
    for (int i = threadIdx.x; i < Dn; i += 256) {
        float v = xr[i];
        s += v;
        s2 = fmaf(v, v, s2);
    }
    #pragma unroll
    for (int off = 16; off; off >>= 1) {
        s  += __shfl_xor_sync(0xffffffffu, s,  off);
        s2 += __shfl_xor_sync(0xffffffffu, s2, off);
    }
    __shared__ float rs[8], rs2[8];
    int w = threadIdx.x >> 5, lane = threadIdx.x & 31;
    if (lane == 0) { rs[w] = s; rs2[w] = s2; }
    __syncthreads();
    if (threadIdx.x < 32) {
        s  = (lane < 8) ? rs[lane]  : 0.f;
        s2 = (lane < 8) ? rs2[lane] : 0.f;
        #pragma unroll
        for (int off = 4; off; off >>= 1) {
            s  += __shfl_xor_sync(0xffffffffu, s,  off);
            s2 += __shfl_xor_sync(0xffffffffu, s2, off);
        }
        if (lane == 0) { rs[0] = s; rs2[0] = s2; }
    }
    __syncthreads();
    float mu  = rs[0] * (1.f / Dn);
    float var = rs2[0] * (1.f / Dn) - mu * mu;
    float inv = rsqrtf(var + 1e-5f);
    for (int i = threadIdx.x; i < Dn; i += 256) {
        orow[i] = (xr[i] - mu) * inv * g[i] + bta[i];
    }
}

// =====================================================================
// TF32 tensor-core GEMM, double-buffered:
//   CTA tile 128x256, BK=16, 256 threads (8 warps, 2x4 of 64x64 warp tiles)
//   one __syncthreads per k-iter; LDG(k+1) overlaps compute(k)
// EPI: 0 = +bias, 1 = +bias +residual, 2 = +bias then exact GELU
// =====================================================================
__device__ __forceinline__ float gelu_exact(float v) {
    return 0.5f * v * (1.0f + erff(v * 0.7071067811865476f));
}
__device__ __forceinline__ uint32_t f2tf(float f) {
    uint32_t u;
    asm("cvt.rna.tf32.f32 %0, %1;" : "=r"(u) : "f"(f));
    return u;
}

#define SPA 136   // A smem row stride (128 + 8): fragment loads conflict-free
#define SPB 264   // B smem row stride (256 + 8)
#define ASZ (16 * SPA)
#define BSZ (16 * SPB)
#define GEMM_SMEM ((2 * ASZ + 2 * BSZ) * 4)

template<int EPI>
__global__ void __launch_bounds__(256) gemm_tf32(
    const float* __restrict__ A, const float* __restrict__ W,
    const float* __restrict__ bias, const float* __restrict__ res,
    float* __restrict__ C, int M, int N, int K)
{
    extern __shared__ uint32_t smem[];
    uint32_t* As = smem;              // [2][16][SPA]  (k-major, transposed)
    uint32_t* Bs = smem + 2 * ASZ;    // [2][16][SPB]

    int tid = threadIdx.x;
    int lane = tid & 31, wid = tid >> 5;
    int warp_m = wid >> 2;            // 0..1
    int warp_n = wid & 3;             // 0..3
    int r = lane >> 2, c = lane & 3;

    int rowBase = blockIdx.y * 128;
    int colBase = blockIdx.x * 256;

    // A: thread owns row tid>>1, k-halves (tid&1)*8
    int arow = tid >> 1;
    int akh  = (tid & 1) * 8;
    const float* Ap = A + (size_t)(rowBase + arow) * K + akh;
    // B: thread handles k = (tid>>6) + 4j, cols n4*4
    int bk0 = tid >> 6;               // 0..3
    int bn4 = tid & 63;               // 0..63
    const float* Bp = W + (size_t)bk0 * N + colBase + bn4 * 4;

    float acc[4][8][4];
    #pragma unroll
    for (int mi = 0; mi < 4; mi++)
        #pragma unroll
        for (int ni = 0; ni < 8; ni++)
            #pragma unroll
            for (int e = 0; e < 4; e++) acc[mi][ni][e] = 0.f;

    float4 apf[2], bpf[4];
    // prologue: load tile 0
    #pragma unroll
    for (int j = 0; j < 2; j++)
        apf[j] = *(const float4*)(Ap + j * 4);
    #pragma unroll
    for (int j = 0; j < 4; j++)
        bpf[j] = *(const float4*)(Bp + (size_t)(4 * j) * N);

    // store tile 0 into buf 0
    #pragma unroll
    for (int j = 0; j < 2; j++) {
        uint32_t* a = &As[(akh + j * 4) * SPA + arow];
        a[0 * SPA] = f2tf(apf[j].x); a[1 * SPA] = f2tf(apf[j].y);
        a[2 * SPA] = f2tf(apf[j].z); a[3 * SPA] = f2tf(apf[j].w);
    }
    #pragma unroll
    for (int j = 0; j < 4; j++) {
        uint4 bb;
        bb.x = f2tf(bpf[j].x); bb.y = f2tf(bpf[j].y);
        bb.z = f2tf(bpf[j].z); bb.w = f2tf(bpf[j].w);
        *(uint4*)&Bs[(bk0 + 4 * j) * SPB + bn4 * 4] = bb;
    }
    __syncthreads();

    int nk = K >> 4;
    int buf = 0;
    for (int kb = 0; kb < nk; kb++) {
        // issue gmem loads for next tile (latency hidden by compute below)
        if (kb + 1 < nk) {
            const float* Apn = Ap + (kb + 1) * 16;
            #pragma unroll
            for (int j = 0; j < 2; j++)
                apf[j] = *(const float4*)(Apn + j * 4);
            const float* Bpn = Bp + (size_t)((kb + 1) * 16) * N;
            #pragma unroll
            for (int j = 0; j < 4; j++)
                bpf[j] = *(const float4*)(Bpn + (size_t)(4 * j) * N);
        }

        // compute current buffer: 2 k-steps of 8
        const uint32_t* Ab = As + buf * ASZ;
        const uint32_t* Bb = Bs + buf * BSZ;
        #pragma unroll
        for (int ks = 0; ks < 2; ks++) {
            int kk = ks * 8;
            uint32_t af[4][4], bf[8][2];
            #pragma unroll
            for (int mi = 0; mi < 4; mi++) {
                int m0 = warp_m * 64 + mi * 16 + r;
                af[mi][0] = Ab[(kk + c) * SPA + m0];
                af[mi][1] = Ab[(kk + c) * SPA + m0 + 8];
                af[mi][2] = Ab[(kk + c + 4) * SPA + m0];
                af[mi][3] = Ab[(kk + c + 4) * SPA + m0 + 8];
            }
            #pragma unroll
            for (int ni = 0; ni < 8; ni++) {
                int n0 = warp_n * 64 + ni * 8 + r;
                bf[ni][0] = Bb[(kk + c) * SPB + n0];
                bf[ni][1] = Bb[(kk + c + 4) * SPB + n0];
            }
            #pragma unroll
            for (int mi = 0; mi < 4; mi++)
                #pragma unroll
                for (int ni = 0; ni < 8; ni++) {
                    asm volatile(
                        "mma.sync.aligned.m16n8k8.row.col.f32.tf32.tf32.f32 "
                        "{%0,%1,%2,%3}, {%4,%5,%6,%7}, {%8,%9}, {%0,%1,%2,%3};\n"
                        : "+f"(acc[mi][ni][0]), "+f"(acc[mi][ni][1]),
                          "+f"(acc[mi][ni][2]), "+f"(acc[mi][ni][3])
                        : "r"(af[mi][0]), "r"(af[mi][1]), "r"(af[mi][2]), "r"(af[mi][3]),
                          "r"(bf[ni][0]), "r"(bf[ni][1]));
                }
        }

        // stage next tile into the other buffer
        if (kb + 1 < nk) {
            int nb = buf ^ 1;
            uint32_t* An = As + nb * ASZ;
            uint32_t* Bw = Bs + nb * BSZ;
            #pragma unroll
            for (int j = 0; j < 2; j++) {
                uint32_t* a = &An[(akh + j * 4) * SPA + arow];
                a[0 * SPA] = f2tf(apf[j].x); a[1 * SPA] = f2tf(apf[j].y);
                a[2 * SPA] = f2tf(apf[j].z); a[3 * SPA] = f2tf(apf[j].w);
            }
            #pragma unroll
            for (int j = 0; j < 4; j++) {
                uint4 bb;
                bb.x = f2tf(bpf[j].x); bb.y = f2tf(bpf[j].y);
                bb.z = f2tf(bpf[j].z); bb.w = f2tf(bpf[j].w);
                *(uint4*)&Bw[(bk0 + 4 * j) * SPB + bn4 * 4] = bb;
            }
            __syncthreads();
            buf = nb;
        }
    }

    // epilogue: c0,c1 at (r, 2c..2c+1); c2,c3 at (r+8, 2c..2c+1)
    #pragma unroll
    for (int mi = 0; mi < 4; mi++) {
        int row0 = rowBase + warp_m * 64 + mi * 16 + r;
        #pragma unroll
        for (int ni = 0; ni < 8; ni++) {
            int col = colBase + warp_n * 64 + ni * 8 + 2 * c;
            float b0 = bias[col], b1 = bias[col + 1];
            float v0 = acc[mi][ni][0] + b0;
            float v1 = acc[mi][ni][1] + b1;
            float v2 = acc[mi][ni][2] + b0;
            float v3 = acc[mi][ni][3] + b1;
            if (EPI == 1) {
                const float2 r0 = *(const float2*)&res[(size_t)row0 * N + col];
                const float2 r1 = *(const float2*)&res[(size_t)(row0 + 8) * N + col];
                v0 += r0.x; v1 += r0.y; v2 += r1.x; v3 += r1.y;
            }
            if (EPI == 2) {
                v0 = gelu_exact(v0); v1 = gelu_exact(v1);
                v2 = gelu_exact(v2); v3 = gelu_exact(v3);
            }
            *(float2*)&C[(size_t)row0 * N + col]       = make_float2(v0, v1);
            *(float2*)&C[(size_t)(row0 + 8) * N + col] = make_float2(v2, v3);
        }
    }
}

// ---------------- Flash attention (causal), fp32 ----------------
// grid: (S/64, B*H); block 256 threads as 16x16; smem 4 tiles of 64x65 f32
#define ATTN_SMEM (4 * 64 * 65 * 4)

__global__ void __launch_bounds__(256) attn_kernel(const float* __restrict__ qkv,
                                                   float* __restrict__ out)
{
    extern __shared__ float sm[];
    float* Qs = sm;
    float* Ks = sm + 64 * 65;
    float* Vs = sm + 2 * 64 * 65;
    float* Ps = sm + 3 * 64 * 65;

    int bh = blockIdx.y;
    int b = bh >> 4;       // H = 16
    int h = bh & 15;
    int q0 = blockIdx.x * 64;
    int tid = threadIdx.x;
    int ty = tid >> 4, tx = tid & 15;

    const size_t rowstride = 3 * Dn;
    const float* base = qkv + (size_t)b * Sn * rowstride + (size_t)h * HDn;

    // load Q tile (64 x 64)
    {
        int r = tid >> 4;
        int c = (tid & 15) * 4;
        #pragma unroll
        for (int it = 0; it < 4; it++) {
            int rr = r + it * 16;
            const float* p = base + (size_t)(q0 + rr) * rowstride + c;
            float4 v = *(const float4*)p;
            float* q = &Qs[rr * 65 + c];
            q[0] = v.x; q[1] = v.y; q[2] = v.z; q[3] = v.w;
        }
    }

    float m[4], l[4], o[4][4];
    #pragma unroll
    for (int i = 0; i < 4; i++) {
        m[i] = -1e30f; l[i] = 0.f;
        #pragma unroll
        for (int j = 0; j < 4; j++) o[i][j] = 0.f;
    }

    int ntiles = blockIdx.x + 1;  // causal: kv tiles with j0 <= q0
    for (int jt = 0; jt < ntiles; jt++) {
        int j0 = jt * 64;
        __syncthreads();  // prior iteration done with Ks/Vs/Ps
        // load K,V tiles
        {
            int r = tid >> 4;
            int c = (tid & 15) * 4;
            #pragma unroll
            for (int it = 0; it < 4; it++) {
                int rr = r + it * 16;
                const float* pk = base + Dn     + (size_t)(j0 + rr) * rowstride + c;
                const float* pv = base + 2 * Dn + (size_t)(j0 + rr) * rowstride + c;
                float4 kv = *(const float4*)pk;
                float4 vv = *(const float4*)pv;
                float* kd = &Ks[rr * 65 + c];
                kd[0] = kv.x; kd[1] = kv.y; kd[2] = kv.z; kd[3] = kv.w;
                float* vd = &Vs[rr * 65 + c];
                vd[0] = vv.x; vd[1] = vv.y; vd[2] = vv.z; vd[3] = vv.w;
            }
        }
        __syncthreads();

        // S = Q K^T (64x64), each thread 4x4
        float s[4][4];
        #pragma unroll
        for (int i = 0; i < 4; i++)
            #pragma unroll
            for (int j = 0; j < 4; j++) s[i][j] = 0.f;
        for (int d = 0; d < 64; d++) {
            float qv[4], kv[4];
            #pragma unroll
            for (int i = 0; i < 4; i++) qv[i] = Qs[(ty * 4 + i) * 65 + d];
            #pragma unroll
            for (int j = 0; j < 4; j++) kv[j] = Ks[(tx * 4 + j) * 65 + d];
            #pragma unroll
            for (int i = 0; i < 4; i++)
                #pragma unroll
                for (int j = 0; j < 4; j++)
                    s[i][j] = fmaf(qv[i], kv[j], s[i][j]);
        }

        bool diag = (jt == blockIdx.x);
        #pragma unroll
        for (int i = 0; i < 4; i++) {
            int qi = ty * 4 + i;
            #pragma unroll
            for (int j = 0; j < 4; j++) {
                int kj = tx * 4 + j;
                float v = s[i][j] * 0.125f;   // 1/sqrt(64)
                if (diag && kj > qi) v = -1e30f;
                s[i][j] = v;
            }
        }

        // online softmax (row groups = 16 lanes sharing ty)
        #pragma unroll
        for (int i = 0; i < 4; i++) {
            float mx = fmaxf(fmaxf(s[i][0], s[i][1]), fmaxf(s[i][2], s[i][3]));
            #pragma unroll
            for (int off = 8; off; off >>= 1)
                mx = fmaxf(mx, __shfl_xor_sync(0xffffffffu, mx, off, 16));
            float mnew = fmaxf(m[i], mx);
            float alpha = __expf(m[i] - mnew);
            m[i] = mnew;
            float rsum = 0.f;
            #pragma unroll
            for (int j = 0; j < 4; j++) {
                float p = __expf(s[i][j] - mnew);
                s[i][j] = p;
                rsum += p;
            }
            #pragma unroll
            for (int off = 8; off; off >>= 1)
                rsum += __shfl_xor_sync(0xffffffffu, rsum, off, 16);
            l[i] = l[i] * alpha + rsum;
            #pragma unroll
            for (int j = 0; j < 4; j++) o[i][j] *= alpha;
        }

        // stage P to smem for the PV product
        #pragma unroll
        for (int i = 0; i < 4; i++)
            #pragma unroll
            for (int j = 0; j < 4; j++)
                Ps[(ty * 4 + i) * 65 + tx * 4 + j] = s[i][j];
        __syncthreads();

        // O += P @ V
        for (int c = 0; c < 64; c++) {
            float pv[4], vv[4];
            #pragma unroll
            for (int i = 0; i < 4; i++) pv[i] = Ps[(ty * 4 + i) * 65 + c];
            #pragma unroll
            for (int j = 0; j < 4; j++) vv[j] = Vs[c * 65 + tx * 4 + j];
            #pragma unroll
            for (int i = 0; i < 4; i++)
                #pragma unroll
                for (int j = 0; j < 4; j++)
                    o[i][j] = fmaf(pv[i], vv[j], o[i][j]);
        }
    }

    // normalize + write [B,S,D] with head offset
    #pragma unroll
    for (int i = 0; i < 4; i++) {
        int qi = q0 + ty * 4 + i;
        float invl = 1.f / l[i];
        #pragma unroll
        for (int j = 0; j < 4; j++) {
            out[((size_t)b * Sn + qi) * Dn + h * HDn + tx * 4 + j] = o[i][j] * invl;
        }
    }
}

// ---------------- launch ----------------
extern "C" void kernel_launch(void* const* d_in, const int* in_sizes, int n_in,
                              void* d_out, int out_size)
{
    const float* x     = (const float*)d_in[0];
    // d_in[1] attention_mask: pure causal, handled analytically
    const float* ln1_g = (const float*)d_in[2];
    const float* ln1_b = (const float*)d_in[3];
    const float* w_qkv = (const float*)d_in[4];
    const float* b_qkv = (const float*)d_in[5];
    const float* w_ao  = (const float*)d_in[6];
    const float* b_ao  = (const float*)d_in[7];
    const float* ln2_g = (const float*)d_in[8];
    const float* ln2_b = (const float*)d_in[9];
    const float* w_fc  = (const float*)d_in[10];
    const float* b_fc  = (const float*)d_in[11];
    const float* w_out = (const float*)d_in[12];
    const float* b_out = (const float*)d_in[13];
    float* out = (float*)d_out;

    float *p_ln1, *p_qkv, *p_att, *p_x1, *p_ln2, *p_fc;
    cudaGetSymbolAddress((void**)&p_ln1, g_ln1);
    cudaGetSymbolAddress((void**)&p_qkv, g_qkv);
    cudaGetSymbolAddress((void**)&p_att, g_att);
    cudaGetSymbolAddress((void**)&p_x1,  g_x1);
    cudaGetSymbolAddress((void**)&p_ln2, g_ln2);
    cudaGetSymbolAddress((void**)&p_fc,  g_fc);

    cudaFuncSetAttribute(attn_kernel, cudaFuncAttributeMaxDynamicSharedMemorySize, ATTN_SMEM);
    cudaFuncSetAttribute(gemm_tf32<0>, cudaFuncAttributeMaxDynamicSharedMemorySize, GEMM_SMEM);
    cudaFuncSetAttribute(gemm_tf32<1>, cudaFuncAttributeMaxDynamicSharedMemorySize, GEMM_SMEM);
    cudaFuncSetAttribute(gemm_tf32<2>, cudaFuncAttributeMaxDynamicSharedMemorySize, GEMM_SMEM);

    // 1) LN1
    ln_kernel<<<Mn, 256>>>(x, ln1_g, ln1_b, p_ln1);
    // 2) QKV = LN1 @ w_qkv + b_qkv   [8192 x 3072]
    gemm_tf32<0><<<dim3(3 * Dn / 256, Mn / 128), 256, GEMM_SMEM>>>(p_ln1, w_qkv, b_qkv, nullptr, p_qkv, Mn, 3 * Dn, Dn);
    // 3) causal flash attention
    attn_kernel<<<dim3(Sn / 64, Bn * Hn), 256, ATTN_SMEM>>>(p_qkv, p_att);
    // 4) x1 = x + att @ w_ao + b_ao
    gemm_tf32<1><<<dim3(Dn / 256, Mn / 128), 256, GEMM_SMEM>>>(p_att, w_ao, b_ao, x, p_x1, Mn, Dn, Dn);
    // 5) LN2
    ln_kernel<<<Mn, 256>>>(p_x1, ln2_g, ln2_b, p_ln2);
    // 6) fc = gelu(LN2 @ w_fc + b_fc)  [8192 x 4096]
    gemm_tf32<2><<<dim3(4 * Dn / 256, Mn / 128), 256, GEMM_SMEM>>>(p_ln2, w_fc, b_fc, nullptr, p_fc, Mn, 4 * Dn, Dn);
    // 7) out = x1 + fc @ w_out + b_out
    gemm_tf32<1><<<dim3(Dn / 256, Mn / 128), 256, GEMM_SMEM>>>(p_fc, w_out, b_out, p_x1, out, Mn, Dn, 4 * Dn);
}

// round 9
// speedup vs baseline: 2.6899x; 1.3129x over previous
#include <cuda_runtime.h>
#include <stdint.h>
#include <math.h>

#define Bn 4
#define Sn 2048
#define Dn 1024
#define Hn 16
#define HDn 64
#define Mn 8192          // B*S

// ---- scratch (allocation-free rule: __device__ globals) ----
__device__ float g_ln1[(size_t)Mn * Dn];        // 32 MB
__device__ float g_qkv[(size_t)Mn * 3 * Dn];    // 96 MB
__device__ float g_att[(size_t)Mn * Dn];        // 32 MB
__device__ float g_x1 [(size_t)Mn * Dn];        // 32 MB
__device__ float g_ln2[(size_t)Mn * Dn];        // 32 MB
__device__ float g_fc [(size_t)Mn * 4 * Dn];    // 128 MB

// ---------------- LayerNorm: one block per row ----------------
__global__ void __launch_bounds__(256) ln_kernel(const float* __restrict__ x,
                                                 const float* __restrict__ g,
                                                 const float* __restrict__ bta,
                                                 float* __restrict__ out)
{
    int row = blockIdx.x;
    const float* xr = x + (size_t)row * Dn;
    float* orow = out + (size_t)row * Dn;
    float s = 0.f, s2 = 0.f;
    for (int i = threadIdx.x; i < Dn; i += 256) {
        float v = xr[i];
        s += v;
        s2 = fmaf(v, v, s2);
    }
    #pragma unroll
    for (int off = 16; off; off >>= 1) {
        s  += __shfl_xor_sync(0xffffffffu, s,  off);
        s2 += __shfl_xor_sync(0xffffffffu, s2, off);
    }
    __shared__ float rs[8], rs2[8];
    int w = threadIdx.x >> 5, lane = threadIdx.x & 31;
    if (lane == 0) { rs[w] = s; rs2[w] = s2; }
    __syncthreads();
    if (threadIdx.x < 32) {
        s  = (lane < 8) ? rs[lane]  : 0.f;
        s2 = (lane < 8) ? rs2[lane] : 0.f;
        #pragma unroll
        for (int off = 4; off; off >>= 1) {
            s  += __shfl_xor_sync(0xffffffffu, s,  off);
            s2 += __shfl_xor_sync(0xffffffffu, s2, off);
        }
        if (lane == 0) { rs[0] = s; rs2[0] = s2; }
    }
    __syncthreads();
    float mu  = rs[0] * (1.f / Dn);
    float var = rs2[0] * (1.f / Dn) - mu * mu;
    float inv = rsqrtf(var + 1e-5f);
    for (int i = threadIdx.x; i < Dn; i += 256) {
        orow[i] = (xr[i] - mu) * inv * g[i] + bta[i];
    }
}

// =====================================================================
// TF32 tensor-core GEMM, double-buffered (unchanged from round 8)
// =====================================================================
__device__ __forceinline__ float gelu_exact(float v) {
    return 0.5f * v * (1.0f + erff(v * 0.7071067811865476f));
}
__device__ __forceinline__ uint32_t f2tf(float f) {
    uint32_t u;
    asm("cvt.rna.tf32.f32 %0, %1;" : "=r"(u) : "f"(f));
    return u;
}
__device__ __forceinline__ void mma_tf32(float* d, const uint32_t* a,
                                         uint32_t b0, uint32_t b1) {
    asm volatile(
        "mma.sync.aligned.m16n8k8.row.col.f32.tf32.tf32.f32 "
        "{%0,%1,%2,%3}, {%4,%5,%6,%7}, {%8,%9}, {%0,%1,%2,%3};\n"
        : "+f"(d[0]), "+f"(d[1]), "+f"(d[2]), "+f"(d[3])
        : "r"(a[0]), "r"(a[1]), "r"(a[2]), "r"(a[3]), "r"(b0), "r"(b1));
}

#define SPA 136   // A smem row stride (128 + 8): fragment loads conflict-free
#define SPB 264   // B smem row stride (256 + 8)
#define ASZ (16 * SPA)
#define BSZ (16 * SPB)
#define GEMM_SMEM ((2 * ASZ + 2 * BSZ) * 4)

template<int EPI>
__global__ void __launch_bounds__(256) gemm_tf32(
    const float* __restrict__ A, const float* __restrict__ W,
    const float* __restrict__ bias, const float* __restrict__ res,
    float* __restrict__ C, int M, int N, int K)
{
    extern __shared__ uint32_t smem[];
    uint32_t* As = smem;              // [2][16][SPA]  (k-major, transposed)
    uint32_t* Bs = smem + 2 * ASZ;    // [2][16][SPB]

    int tid = threadIdx.x;
    int lane = tid & 31, wid = tid >> 5;
    int warp_m = wid >> 2;            // 0..1
    int warp_n = wid & 3;             // 0..3
    int r = lane >> 2, c = lane & 3;

    int rowBase = blockIdx.y * 128;
    int colBase = blockIdx.x * 256;

    int arow = tid >> 1;
    int akh  = (tid & 1) * 8;
    const float* Ap = A + (size_t)(rowBase + arow) * K + akh;
    int bk0 = tid >> 6;               // 0..3
    int bn4 = tid & 63;               // 0..63
    const float* Bp = W + (size_t)bk0 * N + colBase + bn4 * 4;

    float acc[4][8][4];
    #pragma unroll
    for (int mi = 0; mi < 4; mi++)
        #pragma unroll
        for (int ni = 0; ni < 8; ni++)
            #pragma unroll
            for (int e = 0; e < 4; e++) acc[mi][ni][e] = 0.f;

    float4 apf[2], bpf[4];
    #pragma unroll
    for (int j = 0; j < 2; j++)
        apf[j] = *(const float4*)(Ap + j * 4);
    #pragma unroll
    for (int j = 0; j < 4; j++)
        bpf[j] = *(const float4*)(Bp + (size_t)(4 * j) * N);

    #pragma unroll
    for (int j = 0; j < 2; j++) {
        uint32_t* a = &As[(akh + j * 4) * SPA + arow];
        a[0 * SPA] = f2tf(apf[j].x); a[1 * SPA] = f2tf(apf[j].y);
        a[2 * SPA] = f2tf(apf[j].z); a[3 * SPA] = f2tf(apf[j].w);
    }
    #pragma unroll
    for (int j = 0; j < 4; j++) {
        uint4 bb;
        bb.x = f2tf(bpf[j].x); bb.y = f2tf(bpf[j].y);
        bb.z = f2tf(bpf[j].z); bb.w = f2tf(bpf[j].w);
        *(uint4*)&Bs[(bk0 + 4 * j) * SPB + bn4 * 4] = bb;
    }
    __syncthreads();

    int nk = K >> 4;
    int buf = 0;
    for (int kb = 0; kb < nk; kb++) {
        if (kb + 1 < nk) {
            const float* Apn = Ap + (kb + 1) * 16;
            #pragma unroll
            for (int j = 0; j < 2; j++)
                apf[j] = *(const float4*)(Apn + j * 4);
            const float* Bpn = Bp + (size_t)((kb + 1) * 16) * N;
            #pragma unroll
            for (int j = 0; j < 4; j++)
                bpf[j] = *(const float4*)(Bpn + (size_t)(4 * j) * N);
        }

        const uint32_t* Ab = As + buf * ASZ;
        const uint32_t* Bb = Bs + buf * BSZ;
        #pragma unroll
        for (int ks = 0; ks < 2; ks++) {
            int kk = ks * 8;
            uint32_t af[4][4], bf[8][2];
            #pragma unroll
            for (int mi = 0; mi < 4; mi++) {
                int m0 = warp_m * 64 + mi * 16 + r;
                af[mi][0] = Ab[(kk + c) * SPA + m0];
                af[mi][1] = Ab[(kk + c) * SPA + m0 + 8];
                af[mi][2] = Ab[(kk + c + 4) * SPA + m0];
                af[mi][3] = Ab[(kk + c + 4) * SPA + m0 + 8];
            }
            #pragma unroll
            for (int ni = 0; ni < 8; ni++) {
                int n0 = warp_n * 64 + ni * 8 + r;
                bf[ni][0] = Bb[(kk + c) * SPB + n0];
                bf[ni][1] = Bb[(kk + c + 4) * SPB + n0];
            }
            #pragma unroll
            for (int mi = 0; mi < 4; mi++)
                #pragma unroll
                for (int ni = 0; ni < 8; ni++)
                    mma_tf32(acc[mi][ni], af[mi], bf[ni][0], bf[ni][1]);
        }

        if (kb + 1 < nk) {
            int nb = buf ^ 1;
            uint32_t* An = As + nb * ASZ;
            uint32_t* Bw = Bs + nb * BSZ;
            #pragma unroll
            for (int j = 0; j < 2; j++) {
                uint32_t* a = &An[(akh + j * 4) * SPA + arow];
                a[0 * SPA] = f2tf(apf[j].x); a[1 * SPA] = f2tf(apf[j].y);
                a[2 * SPA] = f2tf(apf[j].z); a[3 * SPA] = f2tf(apf[j].w);
            }
            #pragma unroll
            for (int j = 0; j < 4; j++) {
                uint4 bb;
                bb.x = f2tf(bpf[j].x); bb.y = f2tf(bpf[j].y);
                bb.z = f2tf(bpf[j].z); bb.w = f2tf(bpf[j].w);
                *(uint4*)&Bw[(bk0 + 4 * j) * SPB + bn4 * 4] = bb;
            }
            __syncthreads();
            buf = nb;
        }
    }

    #pragma unroll
    for (int mi = 0; mi < 4; mi++) {
        int row0 = rowBase + warp_m * 64 + mi * 16 + r;
        #pragma unroll
        for (int ni = 0; ni < 8; ni++) {
            int col = colBase + warp_n * 64 + ni * 8 + 2 * c;
            float b0 = bias[col], b1 = bias[col + 1];
            float v0 = acc[mi][ni][0] + b0;
            float v1 = acc[mi][ni][1] + b1;
            float v2 = acc[mi][ni][2] + b0;
            float v3 = acc[mi][ni][3] + b1;
            if (EPI == 1) {
                const float2 r0 = *(const float2*)&res[(size_t)row0 * N + col];
                const float2 r1 = *(const float2*)&res[(size_t)(row0 + 8) * N + col];
                v0 += r0.x; v1 += r0.y; v2 += r1.x; v3 += r1.y;
            }
            if (EPI == 2) {
                v0 = gelu_exact(v0); v1 = gelu_exact(v1);
                v2 = gelu_exact(v2); v3 = gelu_exact(v3);
            }
            *(float2*)&C[(size_t)row0 * N + col]       = make_float2(v0, v1);
            *(float2*)&C[(size_t)(row0 + 8) * N + col] = make_float2(v2, v3);
        }
    }
}

// =====================================================================
// TF32 tensor-core flash attention (causal)
//   BQ=128 rows/CTA, 8 warps x 16 rows; BK=64 kv per tile; HD=64
//   S = Q K^T via mma; online softmax on C-fragments; P->smem; O += P V
// =====================================================================
#define SQP 136   // stride for [col][qrow] tiles (128 rows + 8 pad)
#define SKP 72    // stride for 64-wide tiles (64 + 8 pad)
#define ATTN_SMEM ((64 * SQP * 2 + 64 * SKP * 2) * 4)

__global__ void __launch_bounds__(256) attn_tc(const float* __restrict__ qkv,
                                               float* __restrict__ out)
{
    extern __shared__ uint32_t asm_[];
    uint32_t* Qs = asm_;                 // [64 d][128 row] tf32
    uint32_t* Ks = Qs + 64 * SQP;        // [64 d][64 kv]  tf32
    uint32_t* Vs = Ks + 64 * SKP;        // [64 kv][64 hd] tf32
    uint32_t* Ps = Vs + 64 * SKP;        // [64 kv][128 row] tf32 (per-warp rows)

    int bh = blockIdx.y;
    int b = bh >> 4, h = bh & 15;
    int q0 = blockIdx.x * 128;
    int tid = threadIdx.x;
    int lane = tid & 31, wid = tid >> 5;
    int r = lane >> 2, c = lane & 3;
    int mrow = wid * 16 + r;             // this thread's q-row (and +8)

    const size_t rowstride = 3 * Dn;
    const float* base = qkv + (size_t)b * Sn * rowstride + (size_t)h * HDn;

    // load Q tile (128 x 64) transposed k-major, conflict-free scalar STS
    {
        int row = tid & 127, cg = tid >> 7;     // cg 0..1, cols cg*32..+31
        const float* p = base + (size_t)(q0 + row) * rowstride + cg * 32;
        #pragma unroll
        for (int j = 0; j < 8; j++) {
            float4 v = *(const float4*)(p + j * 4);
            int col = cg * 32 + j * 4;
            Qs[(col + 0) * SQP + row] = f2tf(v.x);
            Qs[(col + 1) * SQP + row] = f2tf(v.y);
            Qs[(col + 2) * SQP + row] = f2tf(v.z);
            Qs[(col + 3) * SQP + row] = f2tf(v.w);
        }
    }

    float o[8][4];
    #pragma unroll
    for (int ni = 0; ni < 8; ni++)
        #pragma unroll
        for (int e = 0; e < 4; e++) o[ni][e] = 0.f;
    float m0 = -1e30f, m1 = -1e30f, l0 = 0.f, l1 = 0.f;

    int ntiles = 2 * blockIdx.x + 2;
    for (int jt = 0; jt < ntiles; jt++) {
        int j0 = jt * 64;
        __syncthreads();   // prior iter done with Ks/Vs
        // K: transposed store [d][kv]
        {
            int row = tid & 63, cg = tid >> 6;      // cols cg*16..+15
            const float* pk = base + Dn + (size_t)(j0 + row) * rowstride + cg * 16;
            #pragma unroll
            for (int j = 0; j < 4; j++) {
                float4 v = *(const float4*)(pk + j * 4);
                int col = cg * 16 + j * 4;
                Ks[(col + 0) * SKP + row] = f2tf(v.x);
                Ks[(col + 1) * SKP + row] = f2tf(v.y);
                Ks[(col + 2) * SKP + row] = f2tf(v.z);
                Ks[(col + 3) * SKP + row] = f2tf(v.w);
            }
            // V: natural store [kv][hd]
            int vrow = tid >> 2, vc = (tid & 3) * 16;
            const float* pv = base + 2 * Dn + (size_t)(j0 + vrow) * rowstride + vc;
            #pragma unroll
            for (int j = 0; j < 4; j++) {
                float4 v = *(const float4*)(pv + j * 4);
                uint32_t* d = &Vs[vrow * SKP + vc + j * 4];
                d[0] = f2tf(v.x); d[1] = f2tf(v.y);
                d[2] = f2tf(v.z); d[3] = f2tf(v.w);
            }
        }
        __syncthreads();

        // S = Q K^T  (warp tile 16 x 64)
        float s[8][4];
        #pragma unroll
        for (int ni = 0; ni < 8; ni++)
            #pragma unroll
            for (int e = 0; e < 4; e++) s[ni][e] = 0.f;
        #pragma unroll
        for (int k8 = 0; k8 < 8; k8++) {
            int kk = k8 * 8;
            uint32_t af[4];
            af[0] = Qs[(kk + c) * SQP + mrow];
            af[1] = Qs[(kk + c) * SQP + mrow + 8];
            af[2] = Qs[(kk + c + 4) * SQP + mrow];
            af[3] = Qs[(kk + c + 4) * SQP + mrow + 8];
            #pragma unroll
            for (int ni = 0; ni < 8; ni++) {
                uint32_t b0 = Ks[(kk + c) * SKP + ni * 8 + r];
                uint32_t b1 = Ks[(kk + c + 4) * SKP + ni * 8 + r];
                mma_tf32(s[ni], af, b0, b1);
            }
        }

        // scale + causal mask
        bool diag = (jt >= 2 * (int)blockIdx.x);
        int qr0 = q0 + mrow, qr1 = q0 + mrow + 8;
        #pragma unroll
        for (int ni = 0; ni < 8; ni++) {
            int col = j0 + ni * 8 + 2 * c;
            float v0 = s[ni][0] * 0.125f;
            float v1 = s[ni][1] * 0.125f;
            float v2 = s[ni][2] * 0.125f;
            float v3 = s[ni][3] * 0.125f;
            if (diag) {
                if (col     > qr0) v0 = -1e30f;
                if (col + 1 > qr0) v1 = -1e30f;
                if (col     > qr1) v2 = -1e30f;
                if (col + 1 > qr1) v3 = -1e30f;
            }
            s[ni][0] = v0; s[ni][1] = v1; s[ni][2] = v2; s[ni][3] = v3;
        }

        // online softmax, rows mrow and mrow+8
        float mx0 = -1e30f, mx1 = -1e30f;
        #pragma unroll
        for (int ni = 0; ni < 8; ni++) {
            mx0 = fmaxf(mx0, fmaxf(s[ni][0], s[ni][1]));
            mx1 = fmaxf(mx1, fmaxf(s[ni][2], s[ni][3]));
        }
        #pragma unroll
        for (int off = 1; off <= 2; off <<= 1) {
            mx0 = fmaxf(mx0, __shfl_xor_sync(0xffffffffu, mx0, off));
            mx1 = fmaxf(mx1, __shfl_xor_sync(0xffffffffu, mx1, off));
        }
        float mn0 = fmaxf(m0, mx0), mn1 = fmaxf(m1, mx1);
        float al0 = __expf(m0 - mn0), al1 = __expf(m1 - mn1);
        m0 = mn0; m1 = mn1;
        float sum0 = 0.f, sum1 = 0.f;
        #pragma unroll
        for (int ni = 0; ni < 8; ni++) {
            s[ni][0] = __expf(s[ni][0] - mn0); sum0 += s[ni][0];
            s[ni][1] = __expf(s[ni][1] - mn0); sum0 += s[ni][1];
            s[ni][2] = __expf(s[ni][2] - mn1); sum1 += s[ni][2];
            s[ni][3] = __expf(s[ni][3] - mn1); sum1 += s[ni][3];
        }
        #pragma unroll
        for (int off = 1; off <= 2; off <<= 1) {
            sum0 += __shfl_xor_sync(0xffffffffu, sum0, off);
            sum1 += __shfl_xor_sync(0xffffffffu, sum1, off);
        }
        l0 = l0 * al0 + sum0;
        l1 = l1 * al1 + sum1;
        #pragma unroll
        for (int ni = 0; ni < 8; ni++) {
            o[ni][0] *= al0; o[ni][1] *= al0;
            o[ni][2] *= al1; o[ni][3] *= al1;
        }

        // stage P (tf32) to per-warp-private smem rows
        #pragma unroll
        for (int ni = 0; ni < 8; ni++) {
            int col = ni * 8 + 2 * c;
            Ps[(col    ) * SQP + mrow    ] = f2tf(s[ni][0]);
            Ps[(col + 1) * SQP + mrow    ] = f2tf(s[ni][1]);
            Ps[(col    ) * SQP + mrow + 8] = f2tf(s[ni][2]);
            Ps[(col + 1) * SQP + mrow + 8] = f2tf(s[ni][3]);
        }
        __syncwarp();

        // O += P @ V
        #pragma unroll
        for (int k8 = 0; k8 < 8; k8++) {
            int kk = k8 * 8;
            uint32_t af[4];
            af[0] = Ps[(kk + c) * SQP + mrow];
            af[1] = Ps[(kk + c) * SQP + mrow + 8];
            af[2] = Ps[(kk + c + 4) * SQP + mrow];
            af[3] = Ps[(kk + c + 4) * SQP + mrow + 8];
            #pragma unroll
            for (int ni = 0; ni < 8; ni++) {
                uint32_t b0 = Vs[(kk + c) * SKP + ni * 8 + r];
                uint32_t b1 = Vs[(kk + c + 4) * SKP + ni * 8 + r];
                mma_tf32(o[ni], af, b0, b1);
            }
        }
        __syncwarp();
    }

    // normalize + write [B,S,D] with head offset
    float il0 = 1.f / l0, il1 = 1.f / l1;
    int row0 = q0 + mrow;
    #pragma unroll
    for (int ni = 0; ni < 8; ni++) {
        int col = h * HDn + ni * 8 + 2 * c;
        *(float2*)&out[((size_t)b * Sn + row0) * Dn + col] =
            make_float2(o[ni][0] * il0, o[ni][1] * il0);
        *(float2*)&out[((size_t)b * Sn + row0 + 8) * Dn + col] =
            make_float2(o[ni][2] * il1, o[ni][3] * il1);
    }
}

// ---------------- launch ----------------
extern "C" void kernel_launch(void* const* d_in, const int* in_sizes, int n_in,
                              void* d_out, int out_size)
{
    const float* x     = (const float*)d_in[0];
    // d_in[1] attention_mask: pure causal, handled analytically
    const float* ln1_g = (const float*)d_in[2];
    const float* ln1_b = (const float*)d_in[3];
    const float* w_qkv = (const float*)d_in[4];
    const float* b_qkv = (const float*)d_in[5];
    const float* w_ao  = (const float*)d_in[6];
    const float* b_ao  = (const float*)d_in[7];
    const float* ln2_g = (const float*)d_in[8];
    const float* ln2_b = (const float*)d_in[9];
    const float* w_fc  = (const float*)d_in[10];
    const float* b_fc  = (const float*)d_in[11];
    const float* w_out = (const float*)d_in[12];
    const float* b_out = (const float*)d_in[13];
    float* out = (float*)d_out;

    float *p_ln1, *p_qkv, *p_att, *p_x1, *p_ln2, *p_fc;
    cudaGetSymbolAddress((void**)&p_ln1, g_ln1);
    cudaGetSymbolAddress((void**)&p_qkv, g_qkv);
    cudaGetSymbolAddress((void**)&p_att, g_att);
    cudaGetSymbolAddress((void**)&p_x1,  g_x1);
    cudaGetSymbolAddress((void**)&p_ln2, g_ln2);
    cudaGetSymbolAddress((void**)&p_fc,  g_fc);

    cudaFuncSetAttribute(attn_tc, cudaFuncAttributeMaxDynamicSharedMemorySize, ATTN_SMEM);
    cudaFuncSetAttribute(gemm_tf32<0>, cudaFuncAttributeMaxDynamicSharedMemorySize, GEMM_SMEM);
    cudaFuncSetAttribute(gemm_tf32<1>, cudaFuncAttributeMaxDynamicSharedMemorySize, GEMM_SMEM);
    cudaFuncSetAttribute(gemm_tf32<2>, cudaFuncAttributeMaxDynamicSharedMemorySize, GEMM_SMEM);

    // 1) LN1
    ln_kernel<<<Mn, 256>>>(x, ln1_g, ln1_b, p_ln1);
    // 2) QKV = LN1 @ w_qkv + b_qkv   [8192 x 3072]
    gemm_tf32<0><<<dim3(3 * Dn / 256, Mn / 128), 256, GEMM_SMEM>>>(p_ln1, w_qkv, b_qkv, nullptr, p_qkv, Mn, 3 * Dn, Dn);
    // 3) causal flash attention (tensor cores)
    attn_tc<<<dim3(Sn / 128, Bn * Hn), 256, ATTN_SMEM>>>(p_qkv, p_att);
    // 4) x1 = x + att @ w_ao + b_ao
    gemm_tf32<1><<<dim3(Dn / 256, Mn / 128), 256, GEMM_SMEM>>>(p_att, w_ao, b_ao, x, p_x1, Mn, Dn, Dn);
    // 5) LN2
    ln_kernel<<<Mn, 256>>>(p_x1, ln2_g, ln2_b, p_ln2);
    // 6) fc = gelu(LN2 @ w_fc + b_fc)  [8192 x 4096]
    gemm_tf32<2><<<dim3(4 * Dn / 256, Mn / 128), 256, GEMM_SMEM>>>(p_ln2, w_fc, b_fc, nullptr, p_fc, Mn, 4 * Dn, Dn);
    // 7) out = x1 + fc @ w_out + b_out
    gemm_tf32<1><<<dim3(Dn / 256, Mn / 128), 256, GEMM_SMEM>>>(p_fc, w_out, b_out, p_x1, out, Mn, Dn, 4 * Dn);
}

// round 10
// speedup vs baseline: 2.6930x; 1.0011x over previous
#include <cuda_runtime.h>
#include <stdint.h>
#include <math.h>

#define Bn 4
#define Sn 2048
#define Dn 1024
#define Hn 16
#define HDn 64
#define Mn 8192          // B*S

// ---- scratch (allocation-free rule: __device__ globals) ----
__device__ float g_ln1[(size_t)Mn * Dn];        // 32 MB
__device__ float g_qkv[(size_t)Mn * 3 * Dn];    // 96 MB
__device__ float g_att[(size_t)Mn * Dn];        // 32 MB
__device__ float g_x1 [(size_t)Mn * Dn];        // 32 MB
__device__ float g_ln2[(size_t)Mn * Dn];        // 32 MB
__device__ float g_fc [(size_t)Mn * 4 * Dn];    // 128 MB

// ---------------- LayerNorm: one block per row ----------------
__global__ void __launch_bounds__(256) ln_kernel(const float* __restrict__ x,
                                                 const float* __restrict__ g,
                                                 const float* __restrict__ bta,
                                                 float* __restrict__ out)
{
    int row = blockIdx.x;
    const float* xr = x + (size_t)row * Dn;
    float* orow = out + (size_t)row * Dn;
    float s = 0.f, s2 = 0.f;
    for (int i = threadIdx.x; i < Dn; i += 256) {
        float v = xr[i];
        s += v;
        s2 = fmaf(v, v, s2);
    }
    #pragma unroll
    for (int off = 16; off; off >>= 1) {
        s  += __shfl_xor_sync(0xffffffffu, s,  off);
        s2 += __shfl_xor_sync(0xffffffffu, s2, off);
    }
    __shared__ float rs[8], rs2[8];
    int w = threadIdx.x >> 5, lane = threadIdx.x & 31;
    if (lane == 0) { rs[w] = s; rs2[w] = s2; }
    __syncthreads();
    if (threadIdx.x < 32) {
        s  = (lane < 8) ? rs[lane]  : 0.f;
        s2 = (lane < 8) ? rs2[lane] : 0.f;
        #pragma unroll
        for (int off = 4; off; off >>= 1) {
            s  += __shfl_xor_sync(0xffffffffu, s,  off);
            s2 += __shfl_xor_sync(0xffffffffu, s2, off);
        }
        if (lane == 0) { rs[0] = s; rs2[0] = s2; }
    }
    __syncthreads();
    float mu  = rs[0] * (1.f / Dn);
    float var = rs2[0] * (1.f / Dn) - mu * mu;
    float inv = rsqrtf(var + 1e-5f);
    for (int i = threadIdx.x; i < Dn; i += 256) {
        orow[i] = (xr[i] - mu) * inv * g[i] + bta[i];
    }
}

// =====================================================================
// TF32 tensor-core GEMM, double-buffered, A fragments via LDS.128
//   CTA tile 128x256, BK=16, 256 threads (8 warps, 2x4 of 64x64 warp tiles)
// A smem layout: chunk (k8,c4) of 264 words; word addr within chunk:
//   (m>>4)*32 + (m&7)*4 + ((m>>3)&1)*2 + h    where k = k8*8 + c4 + 4h
// -> per-(lane,mi) A fragment = one aligned LDS.128 (conflict-free)
// =====================================================================
__device__ __forceinline__ float gelu_exact(float v) {
    return 0.5f * v * (1.0f + erff(v * 0.7071067811865476f));
}
__device__ __forceinline__ uint32_t f2tf(float f) {
    uint32_t u;
    asm("cvt.rna.tf32.f32 %0, %1;" : "=r"(u) : "f"(f));
    return u;
}
__device__ __forceinline__ void mma_tf32(float* d, const uint32_t* a,
                                         uint32_t b0, uint32_t b1) {
    asm volatile(
        "mma.sync.aligned.m16n8k8.row.col.f32.tf32.tf32.f32 "
        "{%0,%1,%2,%3}, {%4,%5,%6,%7}, {%8,%9}, {%0,%1,%2,%3};\n"
        : "+f"(d[0]), "+f"(d[1]), "+f"(d[2]), "+f"(d[3])
        : "r"(a[0]), "r"(a[1]), "r"(a[2]), "r"(a[3]), "r"(b0), "r"(b1));
}

#define SPAC 264  // words per (k8,c4) A-chunk: 8 m16-blocks * 32 + 8 pad
#define SPB 264   // B smem row stride (256 + 8)
#define ASZ (8 * SPAC)
#define BSZ (16 * SPB)
#define GEMM_SMEM ((2 * ASZ + 2 * BSZ) * 4)

template<int EPI>
__global__ void __launch_bounds__(256) gemm_tf32(
    const float* __restrict__ A, const float* __restrict__ W,
    const float* __restrict__ bias, const float* __restrict__ res,
    float* __restrict__ C, int M, int N, int K)
{
    extern __shared__ uint32_t smem[];
    uint32_t* As = smem;              // [2][8 chunks][SPAC]
    uint32_t* Bs = smem + 2 * ASZ;    // [2][16][SPB]

    int tid = threadIdx.x;
    int lane = tid & 31, wid = tid >> 5;
    int warp_m = wid >> 2;            // 0..1
    int warp_n = wid & 3;             // 0..3
    int r = lane >> 2, c = lane & 3;

    int rowBase = blockIdx.y * 128;
    int colBase = blockIdx.x * 256;

    int arow = tid >> 1;
    int ak8  = tid & 1;               // k8 of this thread's A elements
    const float* Ap = A + (size_t)(rowBase + arow) * K + ak8 * 8;
    // A store base: chunk (ak8*4 + e), inner (m16*32 + (m&7)*4 + m8*2 + h=j)
    int abase = ak8 * 4 * SPAC + (arow >> 4) * 32 + (arow & 7) * 4 + ((arow >> 3) & 1) * 2;

    int bk0 = tid >> 6;               // 0..3
    int bn4 = tid & 63;               // 0..63
    const float* Bp = W + (size_t)bk0 * N + colBase + bn4 * 4;

    float acc[4][8][4];
    #pragma unroll
    for (int mi = 0; mi < 4; mi++)
        #pragma unroll
        for (int ni = 0; ni < 8; ni++)
            #pragma unroll
            for (int e = 0; e < 4; e++) acc[mi][ni][e] = 0.f;

    float4 apf[2], bpf[4];
    #pragma unroll
    for (int j = 0; j < 2; j++)
        apf[j] = *(const float4*)(Ap + j * 4);
    #pragma unroll
    for (int j = 0; j < 4; j++)
        bpf[j] = *(const float4*)(Bp + (size_t)(4 * j) * N);

    // store tile 0 into buf 0
    #pragma unroll
    for (int j = 0; j < 2; j++) {
        uint32_t* a = &As[abase + j];
        a[0 * SPAC] = f2tf(apf[j].x); a[1 * SPAC] = f2tf(apf[j].y);
        a[2 * SPAC] = f2tf(apf[j].z); a[3 * SPAC] = f2tf(apf[j].w);
    }
    #pragma unroll
    for (int j = 0; j < 4; j++) {
        uint4 bb;
        bb.x = f2tf(bpf[j].x); bb.y = f2tf(bpf[j].y);
        bb.z = f2tf(bpf[j].z); bb.w = f2tf(bpf[j].w);
        *(uint4*)&Bs[(bk0 + 4 * j) * SPB + bn4 * 4] = bb;
    }
    __syncthreads();

    int nk = K >> 4;
    int buf = 0;
    for (int kb = 0; kb < nk; kb++) {
        if (kb + 1 < nk) {
            const float* Apn = Ap + (kb + 1) * 16;
            #pragma unroll
            for (int j = 0; j < 2; j++)
                apf[j] = *(const float4*)(Apn + j * 4);
            const float* Bpn = Bp + (size_t)((kb + 1) * 16) * N;
            #pragma unroll
            for (int j = 0; j < 4; j++)
                bpf[j] = *(const float4*)(Bpn + (size_t)(4 * j) * N);
        }

        const uint32_t* Ab = As + buf * ASZ;
        const uint32_t* Bb = Bs + buf * BSZ;
        #pragma unroll
        for (int ks = 0; ks < 2; ks++) {
            int kk = ks * 8;
            // A fragments: one LDS.128 per mi
            uint32_t af[4][4];
            const uint32_t* Ac = Ab + (ks * 4 + c) * SPAC + r * 4;
            #pragma unroll
            for (int mi = 0; mi < 4; mi++) {
                uint4 va = *(const uint4*)(Ac + (warp_m * 4 + mi) * 32);
                af[mi][0] = va.x;   // (row r,   k c)
                af[mi][1] = va.z;   // (row r+8, k c)
                af[mi][2] = va.y;   // (row r,   k c+4)
                af[mi][3] = va.w;   // (row r+8, k c+4)
            }
            uint32_t bf[8][2];
            #pragma unroll
            for (int ni = 0; ni < 8; ni++) {
                int n0 = warp_n * 64 + ni * 8 + r;
                bf[ni][0] = Bb[(kk + c) * SPB + n0];
                bf[ni][1] = Bb[(kk + c + 4) * SPB + n0];
            }
            #pragma unroll
            for (int mi = 0; mi < 4; mi++)
                #pragma unroll
                for (int ni = 0; ni < 8; ni++)
                    mma_tf32(acc[mi][ni], af[mi], bf[ni][0], bf[ni][1]);
        }

        if (kb + 1 < nk) {
            int nb = buf ^ 1;
            uint32_t* An = As + nb * ASZ;
            uint32_t* Bw = Bs + nb * BSZ;
            #pragma unroll
            for (int j = 0; j < 2; j++) {
                uint32_t* a = &An[abase + j];
                a[0 * SPAC] = f2tf(apf[j].x); a[1 * SPAC] = f2tf(apf[j].y);
                a[2 * SPAC] = f2tf(apf[j].z); a[3 * SPAC] = f2tf(apf[j].w);
            }
            #pragma unroll
            for (int j = 0; j < 4; j++) {
                uint4 bb;
                bb.x = f2tf(bpf[j].x); bb.y = f2tf(bpf[j].y);
                bb.z = f2tf(bpf[j].z); bb.w = f2tf(bpf[j].w);
                *(uint4*)&Bw[(bk0 + 4 * j) * SPB + bn4 * 4] = bb;
            }
            __syncthreads();
            buf = nb;
        }
    }

    #pragma unroll
    for (int mi = 0; mi < 4; mi++) {
        int row0 = rowBase + warp_m * 64 + mi * 16 + r;
        #pragma unroll
        for (int ni = 0; ni < 8; ni++) {
            int col = colBase + warp_n * 64 + ni * 8 + 2 * c;
            float b0 = bias[col], b1 = bias[col + 1];
            float v0 = acc[mi][ni][0] + b0;
            float v1 = acc[mi][ni][1] + b1;
            float v2 = acc[mi][ni][2] + b0;
            float v3 = acc[mi][ni][3] + b1;
            if (EPI == 1) {
                const float2 r0 = *(const float2*)&res[(size_t)row0 * N + col];
                const float2 r1 = *(const float2*)&res[(size_t)(row0 + 8) * N + col];
                v0 += r0.x; v1 += r0.y; v2 += r1.x; v3 += r1.y;
            }
            if (EPI == 2) {
                v0 = gelu_exact(v0); v1 = gelu_exact(v1);
                v2 = gelu_exact(v2); v3 = gelu_exact(v3);
            }
            *(float2*)&C[(size_t)row0 * N + col]       = make_float2(v0, v1);
            *(float2*)&C[(size_t)(row0 + 8) * N + col] = make_float2(v2, v3);
        }
    }
}

// =====================================================================
// TF32 tensor-core flash attention (causal) — unchanged from round 9
// =====================================================================
#define SQP 136
#define SKP 72
#define ATTN_SMEM ((64 * SQP * 2 + 64 * SKP * 2) * 4)

__global__ void __launch_bounds__(256) attn_tc(const float* __restrict__ qkv,
                                               float* __restrict__ out)
{
    extern __shared__ uint32_t asm_[];
    uint32_t* Qs = asm_;                 // [64 d][128 row] tf32
    uint32_t* Ks = Qs + 64 * SQP;        // [64 d][64 kv]  tf32
    uint32_t* Vs = Ks + 64 * SKP;        // [64 kv][64 hd] tf32
    uint32_t* Ps = Vs + 64 * SKP;        // [64 kv][128 row] tf32

    int bh = blockIdx.y;
    int b = bh >> 4, h = bh & 15;
    int q0 = blockIdx.x * 128;
    int tid = threadIdx.x;
    int lane = tid & 31, wid = tid >> 5;
    int r = lane >> 2, c = lane & 3;
    int mrow = wid * 16 + r;

    const size_t rowstride = 3 * Dn;
    const float* base = qkv + (size_t)b * Sn * rowstride + (size_t)h * HDn;

    {
        int row = tid & 127, cg = tid >> 7;
        const float* p = base + (size_t)(q0 + row) * rowstride + cg * 32;
        #pragma unroll
        for (int j = 0; j < 8; j++) {
            float4 v = *(const float4*)(p + j * 4);
            int col = cg * 32 + j * 4;
            Qs[(col + 0) * SQP + row] = f2tf(v.x);
            Qs[(col + 1) * SQP + row] = f2tf(v.y);
            Qs[(col + 2) * SQP + row] = f2tf(v.z);
            Qs[(col + 3) * SQP + row] = f2tf(v.w);
        }
    }

    float o[8][4];
    #pragma unroll
    for (int ni = 0; ni < 8; ni++)
        #pragma unroll
        for (int e = 0; e < 4; e++) o[ni][e] = 0.f;
    float m0 = -1e30f, m1 = -1e30f, l0 = 0.f, l1 = 0.f;

    int ntiles = 2 * blockIdx.x + 2;
    for (int jt = 0; jt < ntiles; jt++) {
        int j0 = jt * 64;
        __syncthreads();
        {
            int row = tid & 63, cg = tid >> 6;
            const float* pk = base + Dn + (size_t)(j0 + row) * rowstride + cg * 16;
            #pragma unroll
            for (int j = 0; j < 4; j++) {
                float4 v = *(const float4*)(pk + j * 4);
                int col = cg * 16 + j * 4;
                Ks[(col + 0) * SKP + row] = f2tf(v.x);
                Ks[(col + 1) * SKP + row] = f2tf(v.y);
                Ks[(col + 2) * SKP + row] = f2tf(v.z);
                Ks[(col + 3) * SKP + row] = f2tf(v.w);
            }
            int vrow = tid >> 2, vc = (tid & 3) * 16;
            const float* pv = base + 2 * Dn + (size_t)(j0 + vrow) * rowstride + vc;
            #pragma unroll
            for (int j = 0; j < 4; j++) {
                float4 v = *(const float4*)(pv + j * 4);
                uint32_t* d = &Vs[vrow * SKP + vc + j * 4];
                d[0] = f2tf(v.x); d[1] = f2tf(v.y);
                d[2] = f2tf(v.z); d[3] = f2tf(v.w);
            }
        }
        __syncthreads();

        float s[8][4];
        #pragma unroll
        for (int ni = 0; ni < 8; ni++)
            #pragma unroll
            for (int e = 0; e < 4; e++) s[ni][e] = 0.f;
        #pragma unroll
        for (int k8 = 0; k8 < 8; k8++) {
            int kk = k8 * 8;
            uint32_t af[4];
            af[0] = Qs[(kk + c) * SQP + mrow];
            af[1] = Qs[(kk + c) * SQP + mrow + 8];
            af[2] = Qs[(kk + c + 4) * SQP + mrow];
            af[3] = Qs[(kk + c + 4) * SQP + mrow + 8];
            #pragma unroll
            for (int ni = 0; ni < 8; ni++) {
                uint32_t b0 = Ks[(kk + c) * SKP + ni * 8 + r];
                uint32_t b1 = Ks[(kk + c + 4) * SKP + ni * 8 + r];
                mma_tf32(s[ni], af, b0, b1);
            }
        }

        bool diag = (jt >= 2 * (int)blockIdx.x);
        int qr0 = q0 + mrow, qr1 = q0 + mrow + 8;
        #pragma unroll
        for (int ni = 0; ni < 8; ni++) {
            int col = j0 + ni * 8 + 2 * c;
            float v0 = s[ni][0] * 0.125f;
            float v1 = s[ni][1] * 0.125f;
            float v2 = s[ni][2] * 0.125f;
            float v3 = s[ni][3] * 0.125f;
            if (diag) {
                if (col     > qr0) v0 = -1e30f;
                if (col + 1 > qr0) v1 = -1e30f;
                if (col     > qr1) v2 = -1e30f;
                if (col + 1 > qr1) v3 = -1e30f;
            }
            s[ni][0] = v0; s[ni][1] = v1; s[ni][2] = v2; s[ni][3] = v3;
        }

        float mx0 = -1e30f, mx1 = -1e30f;
        #pragma unroll
        for (int ni = 0; ni < 8; ni++) {
            mx0 = fmaxf(mx0, fmaxf(s[ni][0], s[ni][1]));
            mx1 = fmaxf(mx1, fmaxf(s[ni][2], s[ni][3]));
        }
        #pragma unroll
        for (int off = 1; off <= 2; off <<= 1) {
            mx0 = fmaxf(mx0, __shfl_xor_sync(0xffffffffu, mx0, off));
            mx1 = fmaxf(mx1, __shfl_xor_sync(0xffffffffu, mx1, off));
        }
        float mn0 = fmaxf(m0, mx0), mn1 = fmaxf(m1, mx1);
        float al0 = __expf(m0 - mn0), al1 = __expf(m1 - mn1);
        m0 = mn0; m1 = mn1;
        float sum0 = 0.f, sum1 = 0.f;
        #pragma unroll
        for (int ni = 0; ni < 8; ni++) {
            s[ni][0] = __expf(s[ni][0] - mn0); sum0 += s[ni][0];
            s[ni][1] = __expf(s[ni][1] - mn0); sum0 += s[ni][1];
            s[ni][2] = __expf(s[ni][2] - mn1); sum1 += s[ni][2];
            s[ni][3] = __expf(s[ni][3] - mn1); sum1 += s[ni][3];
        }
        #pragma unroll
        for (int off = 1; off <= 2; off <<= 1) {
            sum0 += __shfl_xor_sync(0xffffffffu, sum0, off);
            sum1 += __shfl_xor_sync(0xffffffffu, sum1, off);
        }
        l0 = l0 * al0 + sum0;
        l1 = l1 * al1 + sum1;
        #pragma unroll
        for (int ni = 0; ni < 8; ni++) {
            o[ni][0] *= al0; o[ni][1] *= al0;
            o[ni][2] *= al1; o[ni][3] *= al1;
        }

        #pragma unroll
        for (int ni = 0; ni < 8; ni++) {
            int col = ni * 8 + 2 * c;
            Ps[(col    ) * SQP + mrow    ] = f2tf(s[ni][0]);
            Ps[(col + 1) * SQP + mrow    ] = f2tf(s[ni][1]);
            Ps[(col    ) * SQP + mrow + 8] = f2tf(s[ni][2]);
            Ps[(col + 1) * SQP + mrow + 8] = f2tf(s[ni][3]);
        }
        __syncwarp();

        #pragma unroll
        for (int k8 = 0; k8 < 8; k8++) {
            int kk = k8 * 8;
            uint32_t af[4];
            af[0] = Ps[(kk + c) * SQP + mrow];
            af[1] = Ps[(kk + c) * SQP + mrow + 8];
            af[2] = Ps[(kk + c + 4) * SQP + mrow];
            af[3] = Ps[(kk + c + 4) * SQP + mrow + 8];
            #pragma unroll
            for (int ni = 0; ni < 8; ni++) {
                uint32_t b0 = Vs[(kk + c) * SKP + ni * 8 + r];
                uint32_t b1 = Vs[(kk + c + 4) * SKP + ni * 8 + r];
                mma_tf32(o[ni], af, b0, b1);
            }
        }
        __syncwarp();
    }

    float il0 = 1.f / l0, il1 = 1.f / l1;
    int row0 = q0 + mrow;
    #pragma unroll
    for (int ni = 0; ni < 8; ni++) {
        int col = h * HDn + ni * 8 + 2 * c;
        *(float2*)&out[((size_t)b * Sn + row0) * Dn + col] =
            make_float2(o[ni][0] * il0, o[ni][1] * il0);
        *(float2*)&out[((size_t)b * Sn + row0 + 8) * Dn + col] =
            make_float2(o[ni][2] * il1, o[ni][3] * il1);
    }
}

// ---------------- launch ----------------
extern "C" void kernel_launch(void* const* d_in, const int* in_sizes, int n_in,
                              void* d_out, int out_size)
{
    const float* x     = (const float*)d_in[0];
    const float* ln1_g = (const float*)d_in[2];
    const float* ln1_b = (const float*)d_in[3];
    const float* w_qkv = (const float*)d_in[4];
    const float* b_qkv = (const float*)d_in[5];
    const float* w_ao  = (const float*)d_in[6];
    const float* b_ao  = (const float*)d_in[7];
    const float* ln2_g = (const float*)d_in[8];
    const float* ln2_b = (const float*)d_in[9];
    const float* w_fc  = (const float*)d_in[10];
    const float* b_fc  = (const float*)d_in[11];
    const float* w_out = (const float*)d_in[12];
    const float* b_out = (const float*)d_in[13];
    float* out = (float*)d_out;

    float *p_ln1, *p_qkv, *p_att, *p_x1, *p_ln2, *p_fc;
    cudaGetSymbolAddress((void**)&p_ln1, g_ln1);
    cudaGetSymbolAddress((void**)&p_qkv, g_qkv);
    cudaGetSymbolAddress((void**)&p_att, g_att);
    cudaGetSymbolAddress((void**)&p_x1,  g_x1);
    cudaGetSymbolAddress((void**)&p_ln2, g_ln2);
    cudaGetSymbolAddress((void**)&p_fc,  g_fc);

    cudaFuncSetAttribute(attn_tc, cudaFuncAttributeMaxDynamicSharedMemorySize, ATTN_SMEM);
    cudaFuncSetAttribute(gemm_tf32<0>, cudaFuncAttributeMaxDynamicSharedMemorySize, GEMM_SMEM);
    cudaFuncSetAttribute(gemm_tf32<1>, cudaFuncAttributeMaxDynamicSharedMemorySize, GEMM_SMEM);
    cudaFuncSetAttribute(gemm_tf32<2>, cudaFuncAttributeMaxDynamicSharedMemorySize, GEMM_SMEM);

    // 1) LN1
    ln_kernel<<<Mn, 256>>>(x, ln1_g, ln1_b, p_ln1);
    // 2) QKV = LN1 @ w_qkv + b_qkv   [8192 x 3072]
    gemm_tf32<0><<<dim3(3 * Dn / 256, Mn / 128), 256, GEMM_SMEM>>>(p_ln1, w_qkv, b_qkv, nullptr, p_qkv, Mn, 3 * Dn, Dn);
    // 3) causal flash attention (tensor cores)
    attn_tc<<<dim3(Sn / 128, Bn * Hn), 256, ATTN_SMEM>>>(p_qkv, p_att);
    // 4) x1 = x + att @ w_ao + b_ao
    gemm_tf32<1><<<dim3(Dn / 256, Mn / 128), 256, GEMM_SMEM>>>(p_att, w_ao, b_ao, x, p_x1, Mn, Dn, Dn);
    // 5) LN2
    ln_kernel<<<Mn, 256>>>(p_x1, ln2_g, ln2_b, p_ln2);
    // 6) fc = gelu(LN2 @ w_fc + b_fc)  [8192 x 4096]
    gemm_tf32<2><<<dim3(4 * Dn / 256, Mn / 128), 256, GEMM_SMEM>>>(p_ln2, w_fc, b_fc, nullptr, p_fc, Mn, 4 * Dn, Dn);
    // 7) out = x1 + fc @ w_out + b_out
    gemm_tf32<1><<<dim3(Dn / 256, Mn / 128), 256, GEMM_SMEM>>>(p_fc, w_out, b_out, p_x1, out, Mn, Dn, 4 * Dn);
}